// round 12
// baseline (speedup 1.0000x reference)
#include <cuda_runtime.h>
#include <cuda_bf16.h>
#include <cstdint>

#define NEG_SLOPE 0.01f
#define LN_EPS    1e-5f

#define DN 128
#define DE 64
#define DG 32
#define DO 128
#define MAXN 50000
#define PAD 72         // bf16/row for K=64 tiles (edge)
#define PAD2 136       // bf16/row for K=128 tiles (node)

typedef unsigned long long ull;

// ---------------- scratch (device globals) ---------------------------------
__device__ __align__(16) float g_xw1 [MAXN * DO];   // x@Wx + c1 (edge bias)
__device__ __align__(16) float g_xw2 [MAXN * DO];   // x@W2a_x + b2a
__device__ __align__(16) float g_sums[MAXN * DO];
__device__ __align__(16) float g_cnt [MAXN];
__device__ __align__(16) float g_c1  [DO];
__device__ __align__(16) float g_Wc  [DO * DO];     // W1b @ W2a_agg
__device__ __align__(16) float g_c2  [DO];          // b1b @ W2a_agg

// ---------------- warp-MMA helpers (baseline PTX, sm_80+) ------------------
__device__ __forceinline__ void mma16816(
        float& d0, float& d1, float& d2, float& d3,
        uint32_t a0, uint32_t a1, uint32_t a2, uint32_t a3,
        uint32_t b0, uint32_t b1) {
    asm volatile(
        "mma.sync.aligned.m16n8k16.row.col.f32.bf16.bf16.f32 "
        "{%0,%1,%2,%3}, {%4,%5,%6,%7}, {%8,%9}, {%0,%1,%2,%3};"
        : "+f"(d0), "+f"(d1), "+f"(d2), "+f"(d3)
        : "r"(a0), "r"(a1), "r"(a2), "r"(a3), "r"(b0), "r"(b1));
}
__device__ __forceinline__ void ldsm_x4(
        uint32_t& r0, uint32_t& r1, uint32_t& r2, uint32_t& r3, uint32_t addr) {
    asm volatile("ldmatrix.sync.aligned.m8n8.x4.shared.b16 {%0,%1,%2,%3}, [%4];"
        : "=r"(r0), "=r"(r1), "=r"(r2), "=r"(r3) : "r"(addr));
}
__device__ __forceinline__ uint32_t bfpair(float a, float b) {
    __nv_bfloat162 t = __floats2bfloat162_rn(a, b);
    return *reinterpret_cast<uint32_t*>(&t);
}
__device__ __forceinline__ void f4_to_hl(float4 v, ull& ph, ull& pl) {
    __nv_bfloat16 h0 = __float2bfloat16(v.x), h1 = __float2bfloat16(v.y);
    __nv_bfloat16 h2 = __float2bfloat16(v.z), h3 = __float2bfloat16(v.w);
    uint32_t hA = bfpair(v.x, v.y), hB = bfpair(v.z, v.w);
    uint32_t lA = bfpair(v.x - __bfloat162float(h0), v.y - __bfloat162float(h1));
    uint32_t lB = bfpair(v.z - __bfloat162float(h2), v.w - __bfloat162float(h3));
    ph = (ull)hA | ((ull)hB << 32);
    pl = (ull)lA | ((ull)lB << 32);
}
__device__ __forceinline__ void cp16(uint32_t daddr, const void* src) {
    asm volatile("cp.async.cg.shared.global [%0], [%1], 16;"
                 :: "r"(daddr), "l"(src) : "memory");
}

// D[16x128] per warp += A(hi/lo) @ B(hi/lo)^T via ldmatrix fragments.
__device__ __forceinline__ void gemm_hl(
        uint32_t sAh, uint32_t sAl, uint32_t sBh, uint32_t sBl,
        int R, int lane, float d[16][4], int ksteps, int pad) {
    uint32_t aoff = ((R + (lane & 15)) * pad + ((lane >> 4) << 3)) * 2;
    int m = lane >> 3;
    uint32_t boff = (((m >> 1) * 8 + (lane & 7)) * pad + ((m & 1) << 3)) * 2;
#pragma unroll
    for (int ks = 0; ks < 8; ++ks) {
        if (ks >= ksteps) break;
        uint32_t ka = (uint32_t)(ks * 16 * 2);
        uint32_t ah0, ah1, ah2, ah3, al0, al1, al2, al3;
        ldsm_x4(ah0, ah1, ah2, ah3, sAh + aoff + ka);
        ldsm_x4(al0, al1, al2, al3, sAl + aoff + ka);
#pragma unroll
        for (int tt = 0; tt < 8; ++tt) {
            uint32_t bo = boff + (uint32_t)(tt * 16 * pad * 2) + ka;
            uint32_t bh0, bh1, bh2, bh3, bl0, bl1, bl2, bl3;
            ldsm_x4(bh0, bh1, bh2, bh3, sBh + bo);
            ldsm_x4(bl0, bl1, bl2, bl3, sBl + bo);
            int t0 = 2 * tt, t1 = 2 * tt + 1;
            mma16816(d[t0][0], d[t0][1], d[t0][2], d[t0][3], ah0, ah1, ah2, ah3, bh0, bh1);
            mma16816(d[t0][0], d[t0][1], d[t0][2], d[t0][3], al0, al1, al2, al3, bh0, bh1);
            mma16816(d[t0][0], d[t0][1], d[t0][2], d[t0][3], ah0, ah1, ah2, ah3, bl0, bl1);
            mma16816(d[t1][0], d[t1][1], d[t1][2], d[t1][3], ah0, ah1, ah2, ah3, bh2, bh3);
            mma16816(d[t1][0], d[t1][1], d[t1][2], d[t1][3], al0, al1, al2, al3, bh2, bh3);
            mma16816(d[t1][0], d[t1][1], d[t1][2], d[t1][3], ah0, ah1, ah2, ah3, bl2, bl3);
        }
    }
}

// ---------------- kernel 0: c1 = u @ Wu + b1a ------------------------------
__global__ void c1_kernel(const float* __restrict__ W1a,
                          const float* __restrict__ b1a,
                          const float* __restrict__ u) {
    int j = threadIdx.x;
    float acc = b1a[j];
#pragma unroll
    for (int k = 0; k < DG; ++k)
        acc += u[k] * W1a[(DN + DE + k) * DO + j];
    g_c1[j] = acc;
}

// ---------------- kernel W: Wc = W1b @ W2a_agg ; c2 = b1b @ W2a_agg --------
__global__ void wc_kernel(const float* __restrict__ W1b,
                          const float* __restrict__ b1b,
                          const float* __restrict__ W2a) {
    __shared__ float row[DO];
    int j = threadIdx.x;
    int i = blockIdx.x;
    row[j] = (i < DO) ? W1b[i * DO + j] : b1b[j];
    __syncthreads();
    float acc = 0.f;
#pragma unroll 8
    for (int k = 0; k < DO; ++k)
        acc += row[k] * W2a[(DN + k) * DO + j];
    if (i < DO) g_Wc[i * DO + j] = acc;
    else        g_c2[j] = acc;
}

// ---------------- kernel 1: zero scatter buffers ---------------------------
__global__ void zero_kernel(int n_sum, int n_cnt) {
    int i      = blockIdx.x * blockDim.x + threadIdx.x;
    int stride = gridDim.x * blockDim.x;
    for (int idx = i; idx < n_sum; idx += stride) g_sums[idx] = 0.0f;
    for (int idx = i; idx < n_cnt; idx += stride) g_cnt[idx]  = 0.0f;
}

// ---------------- kernel 2: precompute via MMA (R11, unchanged) ------------
__global__ void __launch_bounds__(256, 1) precompute_mma(
        const float* __restrict__ x,
        const float* __restrict__ W1a,
        const float* __restrict__ W2a,
        const float* __restrict__ b2a,
        int N) {
    extern __shared__ __align__(16) char smraw[];
    __nv_bfloat16* Xh  = (__nv_bfloat16*)smraw;
    __nv_bfloat16* Xl  = Xh  + 128 * PAD2;
    __nv_bfloat16* Wxh = Xl  + 128 * PAD2;
    __nv_bfloat16* Wxl = Wxh + 128 * PAD2;
    __nv_bfloat16* W2h = Wxl + 128 * PAD2;
    __nv_bfloat16* W2l = W2h + 128 * PAD2;
    float* b2as = (float*)(W2l + 128 * PAD2);
    float* c1s  = b2as + DO;

    int tid = threadIdx.x;
    for (int idx = tid; idx < DO * DN; idx += 256) {
        int k = idx >> 7, o = idx & 127;
        float v = W1a[idx];
        __nv_bfloat16 h = __float2bfloat16(v);
        Wxh[o * PAD2 + k] = h;
        Wxl[o * PAD2 + k] = __float2bfloat16(v - __bfloat162float(h));
        float w = W2a[idx];
        __nv_bfloat16 h2 = __float2bfloat16(w);
        W2h[o * PAD2 + k] = h2;
        W2l[o * PAD2 + k] = __float2bfloat16(w - __bfloat162float(h2));
    }
    if (tid < DO) {
        b2as[tid] = b2a[tid];
        c1s [tid] = g_c1[tid];
    }
    __syncthreads();

    uint32_t sXh  = (uint32_t)__cvta_generic_to_shared(Xh);
    uint32_t sXl  = (uint32_t)__cvta_generic_to_shared(Xl);
    uint32_t sWxh = (uint32_t)__cvta_generic_to_shared(Wxh);
    uint32_t sWxl = (uint32_t)__cvta_generic_to_shared(Wxl);
    uint32_t sW2h = (uint32_t)__cvta_generic_to_shared(W2h);
    uint32_t sW2l = (uint32_t)__cvta_generic_to_shared(W2l);

    int warp = tid >> 5, lane = tid & 31;
    int R = warp * 16, qr = lane >> 2, qc = lane & 3;
    const float2* b2f2 = (const float2*)b2as;
    const float2* c1f2 = (const float2*)c1s;

    int srow = tid >> 1, skb = (tid & 1) * 64;
    int ntiles = (N + 127) >> 7;
    for (int tile = blockIdx.x; tile < ntiles; tile += gridDim.x) {
        int base = tile << 7;
        {
            int node = base + srow; if (node >= N) node = N - 1;
            const float4* s = (const float4*)(x + (size_t)node * DN + skb);
            ull* ph = (ull*)(Xh + srow * PAD2 + skb);
            ull* pl = (ull*)(Xl + srow * PAD2 + skb);
#pragma unroll
            for (int j = 0; j < 16; ++j) f4_to_hl(s[j], ph[j], pl[j]);
        }
        __syncwarp();

        float d[16][4];
#pragma unroll
        for (int t = 0; t < 16; ++t) d[t][0] = d[t][1] = d[t][2] = d[t][3] = 0.f;
        gemm_hl(sXh, sXl, sWxh, sWxl, R, lane, d, 8, PAD2);
#pragma unroll
        for (int half = 0; half < 2; ++half) {
            int node = base + R + qr + half * 8;
            if (node < N) {
                float2* o = (float2*)(g_xw1 + (size_t)node * DO);
#pragma unroll
                for (int t = 0; t < 16; ++t) {
                    float2 cv = c1f2[t * 4 + qc];
                    o[t * 4 + qc] = make_float2(d[t][half * 2] + cv.x,
                                                d[t][half * 2 + 1] + cv.y);
                }
            }
        }
#pragma unroll
        for (int t = 0; t < 16; ++t) d[t][0] = d[t][1] = d[t][2] = d[t][3] = 0.f;
        gemm_hl(sXh, sXl, sW2h, sW2l, R, lane, d, 8, PAD2);
#pragma unroll
        for (int half = 0; half < 2; ++half) {
            int node = base + R + qr + half * 8;
            if (node < N) {
                float2* o = (float2*)(g_xw2 + (size_t)node * DO);
#pragma unroll
                for (int t = 0; t < 16; ++t) {
                    float2 b = b2f2[t * 4 + qc];
                    o[t * 4 + qc] = make_float2(d[t][half * 2] + b.x,
                                                d[t][half * 2 + 1] + b.y);
                }
            }
        }
        __syncwarp();
    }
}

// ---------------- kernel 3: edge phase (mma + ldmatrix + cp.async pipe) ----
__global__ void __launch_bounds__(256, 2) edge_kernel(
        const int*   __restrict__ ei,
        const float* __restrict__ ea,
        const float* __restrict__ W1a,
        const float* __restrict__ g1,
        const float* __restrict__ be1,
        int E) {
    extern __shared__ __align__(16) char smraw[];
    __nv_bfloat16* EAh   = (__nv_bfloat16*)smraw;          // 18432 B
    __nv_bfloat16* EAl   = EAh + 128 * PAD;
    __nv_bfloat16* WTh   = EAl + 128 * PAD;
    __nv_bfloat16* WTl   = WTh + 128 * PAD;
    float*         EAraw = (float*)(WTl + 128 * PAD);       // 32768 B
    float* g1s  = EAraw + 128 * 64;
    float* be1s = g1s + 128;
    int*   sd   = (int*)(be1s + 128);
    int*   dd   = sd + 128;

    int tid = threadIdx.x;
    for (int idx = tid; idx < DE * DO; idx += 256) {
        int k = idx >> 7, o = idx & 127;
        float v = W1a[(DN + k) * DO + o];
        __nv_bfloat16 h = __float2bfloat16(v);
        WTh[o * PAD + k] = h;
        WTl[o * PAD + k] = __float2bfloat16(v - __bfloat162float(h));
    }
    if (tid < 128) {
        g1s [tid] = g1 [tid];
        be1s[tid] = be1[tid];
    }

    uint32_t sEAh   = (uint32_t)__cvta_generic_to_shared(EAh);
    uint32_t sEAl   = (uint32_t)__cvta_generic_to_shared(EAl);
    uint32_t sWTh   = (uint32_t)__cvta_generic_to_shared(WTh);
    uint32_t sWTl   = (uint32_t)__cvta_generic_to_shared(WTl);
    uint32_t sEAraw = (uint32_t)__cvta_generic_to_shared(EAraw);

    int warp = tid >> 5, lane = tid & 31;
    int R  = warp * 16;
    int qr = lane >> 2, qc = lane & 3;

    const float2* g1f2  = (const float2*)g1s;
    const float2* be1f2 = (const float2*)be1s;

    int ntiles = (E + 127) >> 7;
    int eg_half = tid >> 1;                 // edge-within-tile for staging
    int kb      = (tid & 1) * 32;           // k-offset (floats) for staging
    uint32_t rawdst = sEAraw + (uint32_t)tid * 128;

    // prologue: prefetch first tile
    {
        int tile0 = blockIdx.x;
        if (tile0 < ntiles) {
            int eg = tile0 * 128 + eg_half; if (eg >= E) eg = E - 1;
            const float* src = ea + (size_t)eg * DE + kb;
#pragma unroll
            for (int j = 0; j < 8; ++j) cp16(rawdst + j * 16, src + j * 4);
        }
        asm volatile("cp.async.commit_group;" ::: "memory");
    }

    for (int tile = blockIdx.x; tile < ntiles; tile += gridDim.x) {
        int base = tile << 7;
        asm volatile("cp.async.wait_group 0;" ::: "memory");
        __syncthreads();                      // raw tile ready; prev epilogue done

        // convert raw f32 -> bf16 hi/lo ; load indices
        {
            const float4* s = (const float4*)(EAraw + tid * 32);
            ull* ph = (ull*)(EAh + eg_half * PAD + kb);
            ull* pl = (ull*)(EAl + eg_half * PAD + kb);
#pragma unroll
            for (int j = 0; j < 8; ++j) f4_to_hl(s[j], ph[j], pl[j]);
            if (tid < 128) {
                int eg2 = base + tid; if (eg2 >= E) eg2 = E - 1;
                sd[tid] = ei[eg2];
                dd[tid] = ei[E + eg2];
            }
        }
        __syncthreads();                      // bf16 tiles + idx ready; raw free

        // prefetch next tile into raw buffer (overlaps MMA + epilogue)
        {
            int nt = tile + gridDim.x;
            if (nt < ntiles) {
                int eg = nt * 128 + eg_half; if (eg >= E) eg = E - 1;
                const float* src = ea + (size_t)eg * DE + kb;
#pragma unroll
                for (int j = 0; j < 8; ++j) cp16(rawdst + j * 16, src + j * 4);
            }
            asm volatile("cp.async.commit_group;" ::: "memory");
        }

        float d[16][4];
#pragma unroll
        for (int t = 0; t < 16; ++t) { d[t][0] = d[t][1] = d[t][2] = d[t][3] = 0.f; }
        gemm_hl(sEAh, sEAl, sWTh, sWTl, R, lane, d, 4, PAD);
        __syncthreads();

#pragma unroll
        for (int half = 0; half < 2; ++half) {
            int r   = R + qr + half * 8;
            int src = sd[r], dst = dd[r];
            const float2* bx = (const float2*)(g_xw1 + (size_t)src * DO);

            float sum = 0.f;
#pragma unroll
            for (int ch = 0; ch < 2; ++ch) {
                float2 bb[8];
#pragma unroll
                for (int j = 0; j < 8; ++j)
                    bb[j] = __ldg(bx + (ch * 8 + j) * 4 + qc);
#pragma unroll
                for (int j = 0; j < 8; ++j) {
                    int t = ch * 8 + j;
                    float v0 = d[t][half * 2 + 0] + bb[j].x;
                    float v1 = d[t][half * 2 + 1] + bb[j].y;
                    v0 = v0 >= 0.f ? v0 : NEG_SLOPE * v0;
                    v1 = v1 >= 0.f ? v1 : NEG_SLOPE * v1;
                    d[t][half * 2 + 0] = v0;
                    d[t][half * 2 + 1] = v1;
                    sum += v0 + v1;
                }
            }
            sum += __shfl_xor_sync(0xffffffffu, sum, 1);
            sum += __shfl_xor_sync(0xffffffffu, sum, 2);
            float mu = sum * (1.0f / DO);

            float vv = 0.f;
#pragma unroll
            for (int t = 0; t < 16; ++t) {
                float e0 = d[t][half * 2 + 0] - mu;
                float e1 = d[t][half * 2 + 1] - mu;
                vv += e0 * e0 + e1 * e1;
            }
            vv += __shfl_xor_sync(0xffffffffu, vv, 1);
            vv += __shfl_xor_sync(0xffffffffu, vv, 2);
            float inv = rsqrtf(vv * (1.0f / DO) + LN_EPS);

            if (base + r < E) {
                float* p = g_sums + (size_t)dst * DO;
#pragma unroll
                for (int t = 0; t < 16; ++t) {
                    float2 gv = g1f2[t * 4 + qc];
                    float2 bv = be1f2[t * 4 + qc];
                    float t0 = (d[t][half * 2 + 0] - mu) * inv * gv.x + bv.x;
                    float t1 = (d[t][half * 2 + 1] - mu) * inv * gv.y + bv.y;
                    asm volatile("red.global.add.v2.f32 [%0], {%1, %2};"
                                 :: "l"(p + t * 8 + qc * 2), "f"(t0), "f"(t1) : "memory");
                }
                if (qc == 0) atomicAdd(g_cnt + dst, 1.0f);
            }
        }
    }
}

// ---------------- kernel 4: fused node MLP via MMA (R11, unchanged) --------
__global__ void __launch_bounds__(256, 1) node_fused(
        const float* __restrict__ W2b,
        const float* __restrict__ g2,
        const float* __restrict__ be2,
        const float* __restrict__ b2b,
        float* __restrict__ out,
        int N) {
    extern __shared__ __align__(16) char smraw[];
    __nv_bfloat16* Th  = (__nv_bfloat16*)smraw;
    __nv_bfloat16* Tl  = Th  + 128 * PAD2;
    __nv_bfloat16* Wch = Tl  + 128 * PAD2;
    __nv_bfloat16* Wcl = Wch + 128 * PAD2;
    __nv_bfloat16* Wbh = Wcl + 128 * PAD2;
    __nv_bfloat16* Wbl = Wbh + 128 * PAD2;
    float* cs   = (float*)(Wbl + 128 * PAD2);
    float* c2s  = cs  + 128;
    float* g2s  = c2s + 128;
    float* be2s = g2s + 128;
    float* b2bs = be2s + 128;

    int tid = threadIdx.x;
    for (int idx = tid; idx < DO * DO; idx += 256) {
        int k = idx >> 7, o = idx & 127;
        float v = g_Wc[idx];
        __nv_bfloat16 h = __float2bfloat16(v);
        Wch[o * PAD2 + k] = h;
        Wcl[o * PAD2 + k] = __float2bfloat16(v - __bfloat162float(h));
        float w = W2b[idx];
        __nv_bfloat16 h2 = __float2bfloat16(w);
        Wbh[o * PAD2 + k] = h2;
        Wbl[o * PAD2 + k] = __float2bfloat16(w - __bfloat162float(h2));
    }
    if (tid < DO) {
        c2s [tid] = g_c2[tid];
        g2s [tid] = g2 [tid];
        be2s[tid] = be2[tid];
        b2bs[tid] = b2b[tid];
    }
    __syncthreads();

    uint32_t sTh  = (uint32_t)__cvta_generic_to_shared(Th);
    uint32_t sTl  = (uint32_t)__cvta_generic_to_shared(Tl);
    uint32_t sWch = (uint32_t)__cvta_generic_to_shared(Wch);
    uint32_t sWcl = (uint32_t)__cvta_generic_to_shared(Wcl);
    uint32_t sWbh = (uint32_t)__cvta_generic_to_shared(Wbh);
    uint32_t sWbl = (uint32_t)__cvta_generic_to_shared(Wbl);

    int warp = tid >> 5, lane = tid & 31;
    int R = warp * 16, qr = lane >> 2, qc = lane & 3;
    const float2* c2f2  = (const float2*)c2s;
    const float2* g2f2  = (const float2*)g2s;
    const float2* be2f2 = (const float2*)be2s;
    const float2* b2bf2 = (const float2*)b2bs;

    int srow = tid >> 1, skb = (tid & 1) * 64;
    int ntiles = (N + 127) >> 7;
    for (int tile = blockIdx.x; tile < ntiles; tile += gridDim.x) {
        int base = tile << 7;
        {
            int node = base + srow; if (node >= N) node = N - 1;
            float cn = g_cnt[node];
            float ic = cn > 0.f ? (1.0f / cn) : 0.f;
            if ((tid & 1) == 0) cs[srow] = cn;
            const float4* s = (const float4*)(g_sums + (size_t)node * DO + skb);
            ull* ph = (ull*)(Th + srow * PAD2 + skb);
            ull* pl = (ull*)(Tl + srow * PAD2 + skb);
#pragma unroll
            for (int j = 0; j < 16; ++j) {
                float4 v = s[j];
                v.x *= ic; v.y *= ic; v.z *= ic; v.w *= ic;
                f4_to_hl(v, ph[j], pl[j]);
            }
        }
        __syncwarp();

        float d[16][4];
#pragma unroll
        for (int t = 0; t < 16; ++t) d[t][0] = d[t][1] = d[t][2] = d[t][3] = 0.f;
        gemm_hl(sTh, sTl, sWch, sWcl, R, lane, d, 8, PAD2);
        __syncwarp();

#pragma unroll
        for (int half = 0; half < 2; ++half) {
            int r = R + qr + half * 8;
            int node = base + r; if (node >= N) node = N - 1;
            float cnr = cs[r];
            const float2* xw = (const float2*)(g_xw2 + (size_t)node * DO);

            float sum = 0.f;
#pragma unroll
            for (int t = 0; t < 16; ++t) {
                float2 b  = __ldg(xw + t * 4 + qc);
                float2 cv = c2f2[t * 4 + qc];
                float add0 = cnr > 0.f ? cv.x : 0.f;
                float add1 = cnr > 0.f ? cv.y : 0.f;
                float v0 = d[t][half * 2 + 0] + b.x + add0;
                float v1 = d[t][half * 2 + 1] + b.y + add1;
                v0 = v0 >= 0.f ? v0 : NEG_SLOPE * v0;
                v1 = v1 >= 0.f ? v1 : NEG_SLOPE * v1;
                d[t][half * 2 + 0] = v0;
                d[t][half * 2 + 1] = v1;
                sum += v0 + v1;
            }
            sum += __shfl_xor_sync(0xffffffffu, sum, 1);
            sum += __shfl_xor_sync(0xffffffffu, sum, 2);
            float mu = sum * (1.0f / DO);

            float vv = 0.f;
#pragma unroll
            for (int t = 0; t < 16; ++t) {
                float e0 = d[t][half * 2 + 0] - mu;
                float e1 = d[t][half * 2 + 1] - mu;
                vv += e0 * e0 + e1 * e1;
            }
            vv += __shfl_xor_sync(0xffffffffu, vv, 1);
            vv += __shfl_xor_sync(0xffffffffu, vv, 2);
            float inv = rsqrtf(vv * (1.0f / DO) + LN_EPS);

#pragma unroll
            for (int t = 0; t < 16; ++t) {
                float2 gv = g2f2[t * 4 + qc];
                float2 bv = be2f2[t * 4 + qc];
                float t0 = (d[t][half * 2 + 0] - mu) * inv * gv.x + bv.x;
                float t1 = (d[t][half * 2 + 1] - mu) * inv * gv.y + bv.y;
                __nv_bfloat16 h0 = __float2bfloat16(t0);
                __nv_bfloat16 h1 = __float2bfloat16(t1);
                int off = r * PAD2 + t * 8 + 2 * qc;
                *(uint32_t*)(Th + off) = bfpair(t0, t1);
                *(uint32_t*)(Tl + off) = bfpair(t0 - __bfloat162float(h0),
                                                t1 - __bfloat162float(h1));
            }
        }
        __syncwarp();

#pragma unroll
        for (int t = 0; t < 16; ++t) d[t][0] = d[t][1] = d[t][2] = d[t][3] = 0.f;
        gemm_hl(sTh, sTl, sWbh, sWbl, R, lane, d, 8, PAD2);

#pragma unroll
        for (int half = 0; half < 2; ++half) {
            int node = base + R + qr + half * 8;
            if (node < N) {
                float2* o = (float2*)(out + (size_t)node * DO);
#pragma unroll
                for (int t = 0; t < 16; ++t) {
                    float2 b = b2bf2[t * 4 + qc];
                    o[t * 4 + qc] = make_float2(d[t][half * 2] + b.x,
                                                d[t][half * 2 + 1] + b.y);
                }
            }
        }
        __syncwarp();
    }
}

// ---------------- launcher -------------------------------------------------
static bool g_attr_done = false;

extern "C" void kernel_launch(void* const* d_in, const int* in_sizes, int n_in,
                              void* d_out, int out_size) {
    const float* x   = (const float*)d_in[0];
    const int*   ei  = (const int*)  d_in[1];
    const float* ea  = (const float*)d_in[2];
    const float* u   = (const float*)d_in[3];
    const float* W1a = (const float*)d_in[5];
    const float* b1a = (const float*)d_in[6];
    const float* g1  = (const float*)d_in[7];
    const float* be1 = (const float*)d_in[8];
    const float* W1b = (const float*)d_in[9];
    const float* b1b = (const float*)d_in[10];
    const float* W2a = (const float*)d_in[11];
    const float* b2a = (const float*)d_in[12];
    const float* g2  = (const float*)d_in[13];
    const float* be2 = (const float*)d_in[14];
    const float* W2b = (const float*)d_in[15];
    const float* b2b = (const float*)d_in[16];
    float* out = (float*)d_out;

    int N = in_sizes[0] / DN;
    int E = in_sizes[2] / DE;

    const int PRE2_SMEM = 6 * 128 * PAD2 * 2 + 2 * 128 * 4;                     // 209536
    const int EDGE_SMEM = 4 * 128 * PAD * 2 + 128 * 64 * 4 + 4 * 128 * 4;       // 108544
    const int NF_SMEM   = 6 * 128 * PAD2 * 2 + 5 * 128 * 4;                     // 211456

    if (!g_attr_done) {
        cudaFuncSetAttribute(precompute_mma, cudaFuncAttributeMaxDynamicSharedMemorySize, PRE2_SMEM);
        cudaFuncSetAttribute(edge_kernel,    cudaFuncAttributeMaxDynamicSharedMemorySize, EDGE_SMEM);
        cudaFuncSetAttribute(node_fused,     cudaFuncAttributeMaxDynamicSharedMemorySize, NF_SMEM);
        g_attr_done = true;
    }

    c1_kernel<<<1, 128>>>(W1a, b1a, u);
    wc_kernel<<<129, 128>>>(W1b, b1b, W2a);
    zero_kernel<<<256, 256>>>(N * DO, N);
    precompute_mma<<<148, 256, PRE2_SMEM>>>(x, W1a, W2a, b2a, N);
    edge_kernel<<<296, 256, EDGE_SMEM>>>(ei, ea, W1a, g1, be1, E);
    node_fused<<<148, 256, NF_SMEM>>>(W2b, g2, be2, b2b, out, N);
}

// round 13
// speedup vs baseline: 1.0650x; 1.0650x over previous
#include <cuda_runtime.h>
#include <cuda_bf16.h>
#include <cstdint>

#define NEG_SLOPE 0.01f
#define LN_EPS    1e-5f

#define DN 128
#define DE 64
#define DG 32
#define DO 128
#define MAXN 50000
#define PAD 72         // bf16/row for K=64 tiles (edge)
#define PAD2 136       // bf16/row for K=128 tiles (node)

typedef unsigned long long ull;

// ---------------- scratch (device globals) ---------------------------------
__device__ __align__(16) float g_xw1 [MAXN * DO];   // x@Wx + c1 (edge bias)
__device__ __align__(16) float g_xw2 [MAXN * DO];   // x@W2a_x + b2a
__device__ __align__(16) float g_sums[MAXN * DO];
__device__ __align__(16) float g_cnt [MAXN];
__device__ __align__(16) float g_c1  [DO];
__device__ __align__(16) float g_Wc  [DO * DO];     // W1b @ W2a_agg
__device__ __align__(16) float g_c2  [DO];          // b1b @ W2a_agg

// ---------------- warp-MMA helpers (baseline PTX, sm_80+) ------------------
__device__ __forceinline__ void mma16816(
        float& d0, float& d1, float& d2, float& d3,
        uint32_t a0, uint32_t a1, uint32_t a2, uint32_t a3,
        uint32_t b0, uint32_t b1) {
    asm volatile(
        "mma.sync.aligned.m16n8k16.row.col.f32.bf16.bf16.f32 "
        "{%0,%1,%2,%3}, {%4,%5,%6,%7}, {%8,%9}, {%0,%1,%2,%3};"
        : "+f"(d0), "+f"(d1), "+f"(d2), "+f"(d3)
        : "r"(a0), "r"(a1), "r"(a2), "r"(a3), "r"(b0), "r"(b1));
}
__device__ __forceinline__ void ldsm_x4(
        uint32_t& r0, uint32_t& r1, uint32_t& r2, uint32_t& r3, uint32_t addr) {
    asm volatile("ldmatrix.sync.aligned.m8n8.x4.shared.b16 {%0,%1,%2,%3}, [%4];"
        : "=r"(r0), "=r"(r1), "=r"(r2), "=r"(r3) : "r"(addr));
}
__device__ __forceinline__ uint32_t bfpair(float a, float b) {
    __nv_bfloat162 t = __floats2bfloat162_rn(a, b);
    return *reinterpret_cast<uint32_t*>(&t);
}
__device__ __forceinline__ void f4_to_hl(float4 v, ull& ph, ull& pl) {
    __nv_bfloat16 h0 = __float2bfloat16(v.x), h1 = __float2bfloat16(v.y);
    __nv_bfloat16 h2 = __float2bfloat16(v.z), h3 = __float2bfloat16(v.w);
    uint32_t hA = bfpair(v.x, v.y), hB = bfpair(v.z, v.w);
    uint32_t lA = bfpair(v.x - __bfloat162float(h0), v.y - __bfloat162float(h1));
    uint32_t lB = bfpair(v.z - __bfloat162float(h2), v.w - __bfloat162float(h3));
    ph = (ull)hA | ((ull)hB << 32);
    pl = (ull)lA | ((ull)lB << 32);
}

// D[16x128] per warp += A(hi/lo) @ B(hi/lo)^T via ldmatrix fragments.
__device__ __forceinline__ void gemm_hl(
        uint32_t sAh, uint32_t sAl, uint32_t sBh, uint32_t sBl,
        int R, int lane, float d[16][4], int ksteps, int pad) {
    uint32_t aoff = ((R + (lane & 15)) * pad + ((lane >> 4) << 3)) * 2;
    int m = lane >> 3;
    uint32_t boff = (((m >> 1) * 8 + (lane & 7)) * pad + ((m & 1) << 3)) * 2;
#pragma unroll
    for (int ks = 0; ks < 8; ++ks) {
        if (ks >= ksteps) break;
        uint32_t ka = (uint32_t)(ks * 16 * 2);
        uint32_t ah0, ah1, ah2, ah3, al0, al1, al2, al3;
        ldsm_x4(ah0, ah1, ah2, ah3, sAh + aoff + ka);
        ldsm_x4(al0, al1, al2, al3, sAl + aoff + ka);
#pragma unroll
        for (int tt = 0; tt < 8; ++tt) {
            uint32_t bo = boff + (uint32_t)(tt * 16 * pad * 2) + ka;
            uint32_t bh0, bh1, bh2, bh3, bl0, bl1, bl2, bl3;
            ldsm_x4(bh0, bh1, bh2, bh3, sBh + bo);
            ldsm_x4(bl0, bl1, bl2, bl3, sBl + bo);
            int t0 = 2 * tt, t1 = 2 * tt + 1;
            mma16816(d[t0][0], d[t0][1], d[t0][2], d[t0][3], ah0, ah1, ah2, ah3, bh0, bh1);
            mma16816(d[t0][0], d[t0][1], d[t0][2], d[t0][3], al0, al1, al2, al3, bh0, bh1);
            mma16816(d[t0][0], d[t0][1], d[t0][2], d[t0][3], ah0, ah1, ah2, ah3, bl0, bl1);
            mma16816(d[t1][0], d[t1][1], d[t1][2], d[t1][3], ah0, ah1, ah2, ah3, bh2, bh3);
            mma16816(d[t1][0], d[t1][1], d[t1][2], d[t1][3], al0, al1, al2, al3, bh2, bh3);
            mma16816(d[t1][0], d[t1][1], d[t1][2], d[t1][3], ah0, ah1, ah2, ah3, bl2, bl3);
        }
    }
}

// ---------------- kernel 0: c1 = u @ Wu + b1a ------------------------------
__global__ void c1_kernel(const float* __restrict__ W1a,
                          const float* __restrict__ b1a,
                          const float* __restrict__ u) {
    int j = threadIdx.x;
    float acc = b1a[j];
#pragma unroll
    for (int k = 0; k < DG; ++k)
        acc += u[k] * W1a[(DN + DE + k) * DO + j];
    g_c1[j] = acc;
}

// ---------------- kernel W: Wc = W1b @ W2a_agg ; c2 = b1b @ W2a_agg --------
__global__ void wc_kernel(const float* __restrict__ W1b,
                          const float* __restrict__ b1b,
                          const float* __restrict__ W2a) {
    __shared__ float row[DO];
    int j = threadIdx.x;
    int i = blockIdx.x;
    row[j] = (i < DO) ? W1b[i * DO + j] : b1b[j];
    __syncthreads();
    float acc = 0.f;
#pragma unroll 8
    for (int k = 0; k < DO; ++k)
        acc += row[k] * W2a[(DN + k) * DO + j];
    if (i < DO) g_Wc[i * DO + j] = acc;
    else        g_c2[j] = acc;
}

// ---------------- kernel 1: zero scatter buffers ---------------------------
__global__ void zero_kernel(int n_sum, int n_cnt) {
    int i      = blockIdx.x * blockDim.x + threadIdx.x;
    int stride = gridDim.x * blockDim.x;
    for (int idx = i; idx < n_sum; idx += stride) g_sums[idx] = 0.0f;
    for (int idx = i; idx < n_cnt; idx += stride) g_cnt[idx]  = 0.0f;
}

// ---------------- kernel 2: precompute via MMA (R11, unchanged) ------------
__global__ void __launch_bounds__(256, 1) precompute_mma(
        const float* __restrict__ x,
        const float* __restrict__ W1a,
        const float* __restrict__ W2a,
        const float* __restrict__ b2a,
        int N) {
    extern __shared__ __align__(16) char smraw[];
    __nv_bfloat16* Xh  = (__nv_bfloat16*)smraw;
    __nv_bfloat16* Xl  = Xh  + 128 * PAD2;
    __nv_bfloat16* Wxh = Xl  + 128 * PAD2;
    __nv_bfloat16* Wxl = Wxh + 128 * PAD2;
    __nv_bfloat16* W2h = Wxl + 128 * PAD2;
    __nv_bfloat16* W2l = W2h + 128 * PAD2;
    float* b2as = (float*)(W2l + 128 * PAD2);
    float* c1s  = b2as + DO;

    int tid = threadIdx.x;
    for (int idx = tid; idx < DO * DN; idx += 256) {
        int k = idx >> 7, o = idx & 127;
        float v = W1a[idx];
        __nv_bfloat16 h = __float2bfloat16(v);
        Wxh[o * PAD2 + k] = h;
        Wxl[o * PAD2 + k] = __float2bfloat16(v - __bfloat162float(h));
        float w = W2a[idx];
        __nv_bfloat16 h2 = __float2bfloat16(w);
        W2h[o * PAD2 + k] = h2;
        W2l[o * PAD2 + k] = __float2bfloat16(w - __bfloat162float(h2));
    }
    if (tid < DO) {
        b2as[tid] = b2a[tid];
        c1s [tid] = g_c1[tid];
    }
    __syncthreads();

    uint32_t sXh  = (uint32_t)__cvta_generic_to_shared(Xh);
    uint32_t sXl  = (uint32_t)__cvta_generic_to_shared(Xl);
    uint32_t sWxh = (uint32_t)__cvta_generic_to_shared(Wxh);
    uint32_t sWxl = (uint32_t)__cvta_generic_to_shared(Wxl);
    uint32_t sW2h = (uint32_t)__cvta_generic_to_shared(W2h);
    uint32_t sW2l = (uint32_t)__cvta_generic_to_shared(W2l);

    int warp = tid >> 5, lane = tid & 31;
    int R = warp * 16, qr = lane >> 2, qc = lane & 3;
    const float2* b2f2 = (const float2*)b2as;
    const float2* c1f2 = (const float2*)c1s;

    int srow = tid >> 1, skb = (tid & 1) * 64;
    int ntiles = (N + 127) >> 7;
    for (int tile = blockIdx.x; tile < ntiles; tile += gridDim.x) {
        int base = tile << 7;
        {
            int node = base + srow; if (node >= N) node = N - 1;
            const float4* s = (const float4*)(x + (size_t)node * DN + skb);
            ull* ph = (ull*)(Xh + srow * PAD2 + skb);
            ull* pl = (ull*)(Xl + srow * PAD2 + skb);
#pragma unroll
            for (int j = 0; j < 16; ++j) f4_to_hl(s[j], ph[j], pl[j]);
        }
        __syncwarp();

        float d[16][4];
#pragma unroll
        for (int t = 0; t < 16; ++t) d[t][0] = d[t][1] = d[t][2] = d[t][3] = 0.f;
        gemm_hl(sXh, sXl, sWxh, sWxl, R, lane, d, 8, PAD2);
#pragma unroll
        for (int half = 0; half < 2; ++half) {
            int node = base + R + qr + half * 8;
            if (node < N) {
                float2* o = (float2*)(g_xw1 + (size_t)node * DO);
#pragma unroll
                for (int t = 0; t < 16; ++t) {
                    float2 cv = c1f2[t * 4 + qc];
                    o[t * 4 + qc] = make_float2(d[t][half * 2] + cv.x,
                                                d[t][half * 2 + 1] + cv.y);
                }
            }
        }
#pragma unroll
        for (int t = 0; t < 16; ++t) d[t][0] = d[t][1] = d[t][2] = d[t][3] = 0.f;
        gemm_hl(sXh, sXl, sW2h, sW2l, R, lane, d, 8, PAD2);
#pragma unroll
        for (int half = 0; half < 2; ++half) {
            int node = base + R + qr + half * 8;
            if (node < N) {
                float2* o = (float2*)(g_xw2 + (size_t)node * DO);
#pragma unroll
                for (int t = 0; t < 16; ++t) {
                    float2 b = b2f2[t * 4 + qc];
                    o[t * 4 + qc] = make_float2(d[t][half * 2] + b.x,
                                                d[t][half * 2 + 1] + b.y);
                }
            }
        }
        __syncwarp();
    }
}

// ---------------- kernel 3: edge phase (mma + ldmatrix, v4 atomics) --------
__global__ void __launch_bounds__(256, 2) edge_kernel(
        const int*   __restrict__ ei,
        const float* __restrict__ ea,
        const float* __restrict__ W1a,
        const float* __restrict__ g1,
        const float* __restrict__ be1,
        int E) {
    extern __shared__ __align__(16) char smraw[];
    __nv_bfloat16* EAh = (__nv_bfloat16*)smraw;
    __nv_bfloat16* EAl = EAh + 128 * PAD;
    __nv_bfloat16* WTh = EAl + 128 * PAD;
    __nv_bfloat16* WTl = WTh + 128 * PAD;
    float* g1s  = (float*)(WTl + 128 * PAD);
    float* be1s = g1s + 128;
    int*   sd   = (int*)(be1s + 128);
    int*   dd   = sd + 128;

    int tid = threadIdx.x;
    for (int idx = tid; idx < DE * DO; idx += 256) {
        int k = idx >> 7, o = idx & 127;
        float v = W1a[(DN + k) * DO + o];
        __nv_bfloat16 h = __float2bfloat16(v);
        WTh[o * PAD + k] = h;
        WTl[o * PAD + k] = __float2bfloat16(v - __bfloat162float(h));
    }
    if (tid < 128) {
        g1s [tid] = g1 [tid];
        be1s[tid] = be1[tid];
    }

    uint32_t sEAh = (uint32_t)__cvta_generic_to_shared(EAh);
    uint32_t sEAl = (uint32_t)__cvta_generic_to_shared(EAl);
    uint32_t sWTh = (uint32_t)__cvta_generic_to_shared(WTh);
    uint32_t sWTl = (uint32_t)__cvta_generic_to_shared(WTl);

    int warp = tid >> 5, lane = tid & 31;
    int R  = warp * 16;
    int qr = lane >> 2, qc = lane & 3;

    const float2* g1f2  = (const float2*)g1s;
    const float2* be1f2 = (const float2*)be1s;

    int ntiles = (E + 127) >> 7;
    for (int tile = blockIdx.x; tile < ntiles; tile += gridDim.x) {
        int base = tile << 7;
        __syncthreads();
        {
            int e  = tid >> 1;
            int kb = (tid & 1) * 32;
            int eg = base + e; if (eg >= E) eg = E - 1;
            const float4* s = (const float4*)(ea + (size_t)eg * DE + kb);
            ull* ph = (ull*)(EAh + e * PAD + kb);
            ull* pl = (ull*)(EAl + e * PAD + kb);
#pragma unroll
            for (int j = 0; j < 8; ++j) f4_to_hl(s[j], ph[j], pl[j]);
            if (tid < 128) {
                int eg2 = base + tid; if (eg2 >= E) eg2 = E - 1;
                sd[tid] = ei[eg2];
                dd[tid] = ei[E + eg2];
            }
        }
        __syncthreads();

        float d[16][4];
#pragma unroll
        for (int t = 0; t < 16; ++t) { d[t][0] = d[t][1] = d[t][2] = d[t][3] = 0.f; }
        gemm_hl(sEAh, sEAl, sWTh, sWTl, R, lane, d, 4, PAD);
        __syncthreads();

#pragma unroll
        for (int half = 0; half < 2; ++half) {
            int r   = R + qr + half * 8;
            int src = sd[r], dst = dd[r];
            const float2* bx = (const float2*)(g_xw1 + (size_t)src * DO);

            float sum = 0.f;
#pragma unroll
            for (int t = 0; t < 16; ++t) {
                float2 b = __ldg(bx + t * 4 + qc);
                float v0 = d[t][half * 2 + 0] + b.x;
                float v1 = d[t][half * 2 + 1] + b.y;
                v0 = v0 >= 0.f ? v0 : NEG_SLOPE * v0;
                v1 = v1 >= 0.f ? v1 : NEG_SLOPE * v1;
                d[t][half * 2 + 0] = v0;
                d[t][half * 2 + 1] = v1;
                sum += v0 + v1;
            }
            sum += __shfl_xor_sync(0xffffffffu, sum, 1);
            sum += __shfl_xor_sync(0xffffffffu, sum, 2);
            float mu = sum * (1.0f / DO);

            float vv = 0.f;
#pragma unroll
            for (int t = 0; t < 16; ++t) {
                float e0 = d[t][half * 2 + 0] - mu;
                float e1 = d[t][half * 2 + 1] - mu;
                vv += e0 * e0 + e1 * e1;
            }
            vv += __shfl_xor_sync(0xffffffffu, vv, 1);
            vv += __shfl_xor_sync(0xffffffffu, vv, 2);
            float inv = rsqrtf(vv * (1.0f / DO) + LN_EPS);

            // LN-scale each pair, exchange with quad-partner (qc^1) so even-qc
            // lanes own 4 consecutive floats, then emit half the atomics as v4.
            bool valid = (base + r < E);
            float* p = g_sums + (size_t)dst * DO;
#pragma unroll
            for (int t = 0; t < 16; ++t) {
                float2 gv = g1f2[t * 4 + qc];
                float2 bv = be1f2[t * 4 + qc];
                float f0 = (d[t][half * 2 + 0] - mu) * inv * gv.x + bv.x;
                float f1 = (d[t][half * 2 + 1] - mu) * inv * gv.y + bv.y;
                float p0 = __shfl_xor_sync(0xffffffffu, f0, 1);
                float p1 = __shfl_xor_sync(0xffffffffu, f1, 1);
                if (valid && (qc & 1) == 0) {
                    asm volatile("red.global.add.v4.f32 [%0], {%1, %2, %3, %4};"
                                 :: "l"(p + t * 8 + qc * 2),
                                    "f"(f0), "f"(f1), "f"(p0), "f"(p1) : "memory");
                }
            }
            if (valid && qc == 0) atomicAdd(g_cnt + dst, 1.0f);
        }
    }
}

// ---------------- kernel 4: fused node MLP via MMA (R11, unchanged) --------
__global__ void __launch_bounds__(256, 1) node_fused(
        const float* __restrict__ W2b,
        const float* __restrict__ g2,
        const float* __restrict__ be2,
        const float* __restrict__ b2b,
        float* __restrict__ out,
        int N) {
    extern __shared__ __align__(16) char smraw[];
    __nv_bfloat16* Th  = (__nv_bfloat16*)smraw;
    __nv_bfloat16* Tl  = Th  + 128 * PAD2;
    __nv_bfloat16* Wch = Tl  + 128 * PAD2;
    __nv_bfloat16* Wcl = Wch + 128 * PAD2;
    __nv_bfloat16* Wbh = Wcl + 128 * PAD2;
    __nv_bfloat16* Wbl = Wbh + 128 * PAD2;
    float* cs   = (float*)(Wbl + 128 * PAD2);
    float* c2s  = cs  + 128;
    float* g2s  = c2s + 128;
    float* be2s = g2s + 128;
    float* b2bs = be2s + 128;

    int tid = threadIdx.x;
    for (int idx = tid; idx < DO * DO; idx += 256) {
        int k = idx >> 7, o = idx & 127;
        float v = g_Wc[idx];
        __nv_bfloat16 h = __float2bfloat16(v);
        Wch[o * PAD2 + k] = h;
        Wcl[o * PAD2 + k] = __float2bfloat16(v - __bfloat162float(h));
        float w = W2b[idx];
        __nv_bfloat16 h2 = __float2bfloat16(w);
        Wbh[o * PAD2 + k] = h2;
        Wbl[o * PAD2 + k] = __float2bfloat16(w - __bfloat162float(h2));
    }
    if (tid < DO) {
        c2s [tid] = g_c2[tid];
        g2s [tid] = g2 [tid];
        be2s[tid] = be2[tid];
        b2bs[tid] = b2b[tid];
    }
    __syncthreads();

    uint32_t sTh  = (uint32_t)__cvta_generic_to_shared(Th);
    uint32_t sTl  = (uint32_t)__cvta_generic_to_shared(Tl);
    uint32_t sWch = (uint32_t)__cvta_generic_to_shared(Wch);
    uint32_t sWcl = (uint32_t)__cvta_generic_to_shared(Wcl);
    uint32_t sWbh = (uint32_t)__cvta_generic_to_shared(Wbh);
    uint32_t sWbl = (uint32_t)__cvta_generic_to_shared(Wbl);

    int warp = tid >> 5, lane = tid & 31;
    int R = warp * 16, qr = lane >> 2, qc = lane & 3;
    const float2* c2f2  = (const float2*)c2s;
    const float2* g2f2  = (const float2*)g2s;
    const float2* be2f2 = (const float2*)be2s;
    const float2* b2bf2 = (const float2*)b2bs;

    int srow = tid >> 1, skb = (tid & 1) * 64;
    int ntiles = (N + 127) >> 7;
    for (int tile = blockIdx.x; tile < ntiles; tile += gridDim.x) {
        int base = tile << 7;
        {
            int node = base + srow; if (node >= N) node = N - 1;
            float cn = g_cnt[node];
            float ic = cn > 0.f ? (1.0f / cn) : 0.f;
            if ((tid & 1) == 0) cs[srow] = cn;
            const float4* s = (const float4*)(g_sums + (size_t)node * DO + skb);
            ull* ph = (ull*)(Th + srow * PAD2 + skb);
            ull* pl = (ull*)(Tl + srow * PAD2 + skb);
#pragma unroll
            for (int j = 0; j < 16; ++j) {
                float4 v = s[j];
                v.x *= ic; v.y *= ic; v.z *= ic; v.w *= ic;
                f4_to_hl(v, ph[j], pl[j]);
            }
        }
        __syncwarp();

        float d[16][4];
#pragma unroll
        for (int t = 0; t < 16; ++t) d[t][0] = d[t][1] = d[t][2] = d[t][3] = 0.f;
        gemm_hl(sTh, sTl, sWch, sWcl, R, lane, d, 8, PAD2);
        __syncwarp();

#pragma unroll
        for (int half = 0; half < 2; ++half) {
            int r = R + qr + half * 8;
            int node = base + r; if (node >= N) node = N - 1;
            float cnr = cs[r];
            const float2* xw = (const float2*)(g_xw2 + (size_t)node * DO);

            float sum = 0.f;
#pragma unroll
            for (int t = 0; t < 16; ++t) {
                float2 b  = __ldg(xw + t * 4 + qc);
                float2 cv = c2f2[t * 4 + qc];
                float add0 = cnr > 0.f ? cv.x : 0.f;
                float add1 = cnr > 0.f ? cv.y : 0.f;
                float v0 = d[t][half * 2 + 0] + b.x + add0;
                float v1 = d[t][half * 2 + 1] + b.y + add1;
                v0 = v0 >= 0.f ? v0 : NEG_SLOPE * v0;
                v1 = v1 >= 0.f ? v1 : NEG_SLOPE * v1;
                d[t][half * 2 + 0] = v0;
                d[t][half * 2 + 1] = v1;
                sum += v0 + v1;
            }
            sum += __shfl_xor_sync(0xffffffffu, sum, 1);
            sum += __shfl_xor_sync(0xffffffffu, sum, 2);
            float mu = sum * (1.0f / DO);

            float vv = 0.f;
#pragma unroll
            for (int t = 0; t < 16; ++t) {
                float e0 = d[t][half * 2 + 0] - mu;
                float e1 = d[t][half * 2 + 1] - mu;
                vv += e0 * e0 + e1 * e1;
            }
            vv += __shfl_xor_sync(0xffffffffu, vv, 1);
            vv += __shfl_xor_sync(0xffffffffu, vv, 2);
            float inv = rsqrtf(vv * (1.0f / DO) + LN_EPS);

#pragma unroll
            for (int t = 0; t < 16; ++t) {
                float2 gv = g2f2[t * 4 + qc];
                float2 bv = be2f2[t * 4 + qc];
                float t0 = (d[t][half * 2 + 0] - mu) * inv * gv.x + bv.x;
                float t1 = (d[t][half * 2 + 1] - mu) * inv * gv.y + bv.y;
                __nv_bfloat16 h0 = __float2bfloat16(t0);
                __nv_bfloat16 h1 = __float2bfloat16(t1);
                int off = r * PAD2 + t * 8 + 2 * qc;
                *(uint32_t*)(Th + off) = bfpair(t0, t1);
                *(uint32_t*)(Tl + off) = bfpair(t0 - __bfloat162float(h0),
                                                t1 - __bfloat162float(h1));
            }
        }
        __syncwarp();

#pragma unroll
        for (int t = 0; t < 16; ++t) d[t][0] = d[t][1] = d[t][2] = d[t][3] = 0.f;
        gemm_hl(sTh, sTl, sWbh, sWbl, R, lane, d, 8, PAD2);

#pragma unroll
        for (int half = 0; half < 2; ++half) {
            int node = base + R + qr + half * 8;
            if (node < N) {
                float2* o = (float2*)(out + (size_t)node * DO);
#pragma unroll
                for (int t = 0; t < 16; ++t) {
                    float2 b = b2bf2[t * 4 + qc];
                    o[t * 4 + qc] = make_float2(d[t][half * 2] + b.x,
                                                d[t][half * 2 + 1] + b.y);
                }
            }
        }
        __syncwarp();
    }
}

// ---------------- launcher -------------------------------------------------
static bool g_attr_done = false;

extern "C" void kernel_launch(void* const* d_in, const int* in_sizes, int n_in,
                              void* d_out, int out_size) {
    const float* x   = (const float*)d_in[0];
    const int*   ei  = (const int*)  d_in[1];
    const float* ea  = (const float*)d_in[2];
    const float* u   = (const float*)d_in[3];
    const float* W1a = (const float*)d_in[5];
    const float* b1a = (const float*)d_in[6];
    const float* g1  = (const float*)d_in[7];
    const float* be1 = (const float*)d_in[8];
    const float* W1b = (const float*)d_in[9];
    const float* b1b = (const float*)d_in[10];
    const float* W2a = (const float*)d_in[11];
    const float* b2a = (const float*)d_in[12];
    const float* g2  = (const float*)d_in[13];
    const float* be2 = (const float*)d_in[14];
    const float* W2b = (const float*)d_in[15];
    const float* b2b = (const float*)d_in[16];
    float* out = (float*)d_out;

    int N = in_sizes[0] / DN;
    int E = in_sizes[2] / DE;

    const int PRE2_SMEM = 6 * 128 * PAD2 * 2 + 2 * 128 * 4;                // 209536
    const int EDGE_SMEM = 4 * 128 * PAD * 2 + 2 * 128 * 4 + 2 * 128 * 4;   // 75776
    const int NF_SMEM   = 6 * 128 * PAD2 * 2 + 5 * 128 * 4;                // 211456

    if (!g_attr_done) {
        cudaFuncSetAttribute(precompute_mma, cudaFuncAttributeMaxDynamicSharedMemorySize, PRE2_SMEM);
        cudaFuncSetAttribute(edge_kernel,    cudaFuncAttributeMaxDynamicSharedMemorySize, EDGE_SMEM);
        cudaFuncSetAttribute(node_fused,     cudaFuncAttributeMaxDynamicSharedMemorySize, NF_SMEM);
        g_attr_done = true;
    }

    c1_kernel<<<1, 128>>>(W1a, b1a, u);
    wc_kernel<<<129, 128>>>(W1b, b1b, W2a);
    zero_kernel<<<256, 256>>>(N * DO, N);
    precompute_mma<<<148, 256, PRE2_SMEM>>>(x, W1a, W2a, b2a, N);
    edge_kernel<<<296, 256, EDGE_SMEM>>>(ei, ea, W1a, g1, be1, E);
    node_fused<<<148, 256, NF_SMEM>>>(W2b, g2, be2, b2b, out, N);
}

// round 14
// speedup vs baseline: 1.1659x; 1.0947x over previous
#include <cuda_runtime.h>
#include <cuda_bf16.h>
#include <cstdint>

#define NEG_SLOPE 0.01f
#define LN_EPS    1e-5f

#define DN 128
#define DE 64
#define DG 32
#define DO 128
#define MAXN 50000
#define PAD 72         // bf16/row for K=64 tiles (edge)
#define PAD2 136       // bf16/row for K=128 tiles (node)

typedef unsigned long long ull;

// ---------------- scratch (device globals) ---------------------------------
__device__ __align__(16) float g_xw1 [MAXN * DO];   // x@Wx + c1 (edge bias)
__device__ __align__(16) float g_xw2 [MAXN * DO];   // x@W2a_x + b2a
__device__ __align__(16) float g_sums[MAXN * DO];
__device__ __align__(16) float g_cnt [MAXN];
__device__ __align__(16) float g_c1  [DO];
__device__ __align__(16) float g_Wc  [DO * DO];     // W1b @ W2a_agg
__device__ __align__(16) float g_c2  [DO];          // b1b @ W2a_agg

// ---------------- warp-MMA helpers (baseline PTX, sm_80+) ------------------
__device__ __forceinline__ void mma16816(
        float& d0, float& d1, float& d2, float& d3,
        uint32_t a0, uint32_t a1, uint32_t a2, uint32_t a3,
        uint32_t b0, uint32_t b1) {
    asm volatile(
        "mma.sync.aligned.m16n8k16.row.col.f32.bf16.bf16.f32 "
        "{%0,%1,%2,%3}, {%4,%5,%6,%7}, {%8,%9}, {%0,%1,%2,%3};"
        : "+f"(d0), "+f"(d1), "+f"(d2), "+f"(d3)
        : "r"(a0), "r"(a1), "r"(a2), "r"(a3), "r"(b0), "r"(b1));
}
__device__ __forceinline__ void ldsm_x4(
        uint32_t& r0, uint32_t& r1, uint32_t& r2, uint32_t& r3, uint32_t addr) {
    asm volatile("ldmatrix.sync.aligned.m8n8.x4.shared.b16 {%0,%1,%2,%3}, [%4];"
        : "=r"(r0), "=r"(r1), "=r"(r2), "=r"(r3) : "r"(addr));
}
__device__ __forceinline__ uint32_t bfpair(float a, float b) {
    __nv_bfloat162 t = __floats2bfloat162_rn(a, b);
    return *reinterpret_cast<uint32_t*>(&t);
}
__device__ __forceinline__ void f4_to_hl(float4 v, ull& ph, ull& pl) {
    __nv_bfloat16 h0 = __float2bfloat16(v.x), h1 = __float2bfloat16(v.y);
    __nv_bfloat16 h2 = __float2bfloat16(v.z), h3 = __float2bfloat16(v.w);
    uint32_t hA = bfpair(v.x, v.y), hB = bfpair(v.z, v.w);
    uint32_t lA = bfpair(v.x - __bfloat162float(h0), v.y - __bfloat162float(h1));
    uint32_t lB = bfpair(v.z - __bfloat162float(h2), v.w - __bfloat162float(h3));
    ph = (ull)hA | ((ull)hB << 32);
    pl = (ull)lA | ((ull)lB << 32);
}

// D[16x128] per warp += A(hi/lo) @ B(hi/lo)^T via ldmatrix fragments.
__device__ __forceinline__ void gemm_hl(
        uint32_t sAh, uint32_t sAl, uint32_t sBh, uint32_t sBl,
        int R, int lane, float d[16][4], int ksteps, int pad) {
    uint32_t aoff = ((R + (lane & 15)) * pad + ((lane >> 4) << 3)) * 2;
    int m = lane >> 3;
    uint32_t boff = (((m >> 1) * 8 + (lane & 7)) * pad + ((m & 1) << 3)) * 2;
#pragma unroll
    for (int ks = 0; ks < 8; ++ks) {
        if (ks >= ksteps) break;
        uint32_t ka = (uint32_t)(ks * 16 * 2);
        uint32_t ah0, ah1, ah2, ah3, al0, al1, al2, al3;
        ldsm_x4(ah0, ah1, ah2, ah3, sAh + aoff + ka);
        ldsm_x4(al0, al1, al2, al3, sAl + aoff + ka);
#pragma unroll
        for (int tt = 0; tt < 8; ++tt) {
            uint32_t bo = boff + (uint32_t)(tt * 16 * pad * 2) + ka;
            uint32_t bh0, bh1, bh2, bh3, bl0, bl1, bl2, bl3;
            ldsm_x4(bh0, bh1, bh2, bh3, sBh + bo);
            ldsm_x4(bl0, bl1, bl2, bl3, sBl + bo);
            int t0 = 2 * tt, t1 = 2 * tt + 1;
            mma16816(d[t0][0], d[t0][1], d[t0][2], d[t0][3], ah0, ah1, ah2, ah3, bh0, bh1);
            mma16816(d[t0][0], d[t0][1], d[t0][2], d[t0][3], al0, al1, al2, al3, bh0, bh1);
            mma16816(d[t0][0], d[t0][1], d[t0][2], d[t0][3], ah0, ah1, ah2, ah3, bl0, bl1);
            mma16816(d[t1][0], d[t1][1], d[t1][2], d[t1][3], ah0, ah1, ah2, ah3, bh2, bh3);
            mma16816(d[t1][0], d[t1][1], d[t1][2], d[t1][3], al0, al1, al2, al3, bh2, bh3);
            mma16816(d[t1][0], d[t1][1], d[t1][2], d[t1][3], ah0, ah1, ah2, ah3, bl2, bl3);
        }
    }
}

// ---------------- kernel 0: c1 = u @ Wu + b1a ------------------------------
__global__ void c1_kernel(const float* __restrict__ W1a,
                          const float* __restrict__ b1a,
                          const float* __restrict__ u) {
    int j = threadIdx.x;
    float acc = b1a[j];
#pragma unroll
    for (int k = 0; k < DG; ++k)
        acc += u[k] * W1a[(DN + DE + k) * DO + j];
    g_c1[j] = acc;
}

// ---------------- kernel W: Wc = W1b @ W2a_agg ; c2 = b1b @ W2a_agg --------
__global__ void wc_kernel(const float* __restrict__ W1b,
                          const float* __restrict__ b1b,
                          const float* __restrict__ W2a) {
    __shared__ float row[DO];
    int j = threadIdx.x;
    int i = blockIdx.x;
    row[j] = (i < DO) ? W1b[i * DO + j] : b1b[j];
    __syncthreads();
    float acc = 0.f;
#pragma unroll 8
    for (int k = 0; k < DO; ++k)
        acc += row[k] * W2a[(DN + k) * DO + j];
    if (i < DO) g_Wc[i * DO + j] = acc;
    else        g_c2[j] = acc;
}

// ---------------- kernel 2: precompute via MMA + scatter-buffer zeroing ----
// zeroes g_sums/g_cnt, then: xw1 = x@Wx + c1 ; xw2 = x@W2a_x + b2a
__global__ void __launch_bounds__(256, 1) precompute_mma(
        const float* __restrict__ x,
        const float* __restrict__ W1a,
        const float* __restrict__ W2a,
        const float* __restrict__ b2a,
        int N) {
    extern __shared__ __align__(16) char smraw[];
    __nv_bfloat16* Xh  = (__nv_bfloat16*)smraw;
    __nv_bfloat16* Xl  = Xh  + 128 * PAD2;
    __nv_bfloat16* Wxh = Xl  + 128 * PAD2;
    __nv_bfloat16* Wxl = Wxh + 128 * PAD2;
    __nv_bfloat16* W2h = Wxl + 128 * PAD2;
    __nv_bfloat16* W2l = W2h + 128 * PAD2;
    float* b2as = (float*)(W2l + 128 * PAD2);
    float* c1s  = b2as + DO;

    int tid = threadIdx.x;

    // ---- zero scatter buffers (replaces zero_kernel) ----
    {
        int gid = blockIdx.x * blockDim.x + tid;
        int gth = gridDim.x * blockDim.x;
        float4 z = make_float4(0.f, 0.f, 0.f, 0.f);
        int nq = N * DO / 4;
        for (int i = gid; i < nq; i += gth) ((float4*)g_sums)[i] = z;
        for (int i = gid; i < N;  i += gth) g_cnt[i] = 0.f;
    }

    for (int idx = tid; idx < DO * DN; idx += 256) {
        int k = idx >> 7, o = idx & 127;
        float v = W1a[idx];
        __nv_bfloat16 h = __float2bfloat16(v);
        Wxh[o * PAD2 + k] = h;
        Wxl[o * PAD2 + k] = __float2bfloat16(v - __bfloat162float(h));
        float w = W2a[idx];
        __nv_bfloat16 h2 = __float2bfloat16(w);
        W2h[o * PAD2 + k] = h2;
        W2l[o * PAD2 + k] = __float2bfloat16(w - __bfloat162float(h2));
    }
    if (tid < DO) {
        b2as[tid] = b2a[tid];
        c1s [tid] = g_c1[tid];
    }
    __syncthreads();

    uint32_t sXh  = (uint32_t)__cvta_generic_to_shared(Xh);
    uint32_t sXl  = (uint32_t)__cvta_generic_to_shared(Xl);
    uint32_t sWxh = (uint32_t)__cvta_generic_to_shared(Wxh);
    uint32_t sWxl = (uint32_t)__cvta_generic_to_shared(Wxl);
    uint32_t sW2h = (uint32_t)__cvta_generic_to_shared(W2h);
    uint32_t sW2l = (uint32_t)__cvta_generic_to_shared(W2l);

    int warp = tid >> 5, lane = tid & 31;
    int R = warp * 16, qr = lane >> 2, qc = lane & 3;
    const float2* b2f2 = (const float2*)b2as;
    const float2* c1f2 = (const float2*)c1s;

    int srow = tid >> 1, skb = (tid & 1) * 64;
    int ntiles = (N + 127) >> 7;
    for (int tile = blockIdx.x; tile < ntiles; tile += gridDim.x) {
        int base = tile << 7;
        {
            int node = base + srow; if (node >= N) node = N - 1;
            const float4* s = (const float4*)(x + (size_t)node * DN + skb);
            ull* ph = (ull*)(Xh + srow * PAD2 + skb);
            ull* pl = (ull*)(Xl + srow * PAD2 + skb);
#pragma unroll
            for (int j = 0; j < 16; ++j) f4_to_hl(s[j], ph[j], pl[j]);
        }
        __syncwarp();

        float d[16][4];
#pragma unroll
        for (int t = 0; t < 16; ++t) d[t][0] = d[t][1] = d[t][2] = d[t][3] = 0.f;
        gemm_hl(sXh, sXl, sWxh, sWxl, R, lane, d, 8, PAD2);
#pragma unroll
        for (int half = 0; half < 2; ++half) {
            int node = base + R + qr + half * 8;
            if (node < N) {
                float2* o = (float2*)(g_xw1 + (size_t)node * DO);
#pragma unroll
                for (int t = 0; t < 16; ++t) {
                    float2 cv = c1f2[t * 4 + qc];
                    o[t * 4 + qc] = make_float2(d[t][half * 2] + cv.x,
                                                d[t][half * 2 + 1] + cv.y);
                }
            }
        }
#pragma unroll
        for (int t = 0; t < 16; ++t) d[t][0] = d[t][1] = d[t][2] = d[t][3] = 0.f;
        gemm_hl(sXh, sXl, sW2h, sW2l, R, lane, d, 8, PAD2);
#pragma unroll
        for (int half = 0; half < 2; ++half) {
            int node = base + R + qr + half * 8;
            if (node < N) {
                float2* o = (float2*)(g_xw2 + (size_t)node * DO);
#pragma unroll
                for (int t = 0; t < 16; ++t) {
                    float2 b = b2f2[t * 4 + qc];
                    o[t * 4 + qc] = make_float2(d[t][half * 2] + b.x,
                                                d[t][half * 2 + 1] + b.y);
                }
            }
        }
        __syncwarp();
    }
}

// ---------------- kernel 3: edge phase (warp-decoupled, no block syncs) ----
__global__ void __launch_bounds__(256, 2) edge_kernel(
        const int*   __restrict__ ei,
        const float* __restrict__ ea,
        const float* __restrict__ W1a,
        const float* __restrict__ g1,
        const float* __restrict__ be1,
        int E) {
    extern __shared__ __align__(16) char smraw[];
    __nv_bfloat16* EAh = (__nv_bfloat16*)smraw;
    __nv_bfloat16* EAl = EAh + 128 * PAD;
    __nv_bfloat16* WTh = EAl + 128 * PAD;
    __nv_bfloat16* WTl = WTh + 128 * PAD;
    float* g1s  = (float*)(WTl + 128 * PAD);
    float* be1s = g1s + 128;
    int*   sd   = (int*)(be1s + 128);
    int*   dd   = sd + 128;

    int tid = threadIdx.x;
    for (int idx = tid; idx < DE * DO; idx += 256) {
        int k = idx >> 7, o = idx & 127;
        float v = W1a[(DN + k) * DO + o];
        __nv_bfloat16 h = __float2bfloat16(v);
        WTh[o * PAD + k] = h;
        WTl[o * PAD + k] = __float2bfloat16(v - __bfloat162float(h));
    }
    if (tid < 128) {
        g1s [tid] = g1 [tid];
        be1s[tid] = be1[tid];
    }
    __syncthreads();   // weights + LN vectors visible to all warps (once)

    uint32_t sEAh = (uint32_t)__cvta_generic_to_shared(EAh);
    uint32_t sEAl = (uint32_t)__cvta_generic_to_shared(EAl);
    uint32_t sWTh = (uint32_t)__cvta_generic_to_shared(WTh);
    uint32_t sWTl = (uint32_t)__cvta_generic_to_shared(WTl);

    int warp = tid >> 5, lane = tid & 31;
    int R  = warp * 16;
    int qr = lane >> 2, qc = lane & 3;

    const float2* g1f2  = (const float2*)g1s;
    const float2* be1f2 = (const float2*)be1s;

    // warp-local staging geometry: lane l -> edge R+(l>>1), k-half (l&1)*32
    int e_loc = R + (lane >> 1);
    int kb    = (lane & 1) * 32;

    int ntiles = (E + 127) >> 7;
    for (int tile = blockIdx.x; tile < ntiles; tile += gridDim.x) {
        int base = tile << 7;
        __syncwarp();   // own warp's prior-tile smem reads done before overwrite

        // ---- stage own 16 EA rows + own sd/dd (warp-private) ----
        {
            int eg = base + e_loc; if (eg >= E) eg = E - 1;
            const float4* s = (const float4*)(ea + (size_t)eg * DE + kb);
            ull* ph = (ull*)(EAh + e_loc * PAD + kb);
            ull* pl = (ull*)(EAl + e_loc * PAD + kb);
#pragma unroll
            for (int j = 0; j < 8; ++j) f4_to_hl(s[j], ph[j], pl[j]);
            if (lane < 16) {
                int eg2 = base + R + lane; if (eg2 >= E) eg2 = E - 1;
                sd[R + lane] = ei[eg2];
            } else {
                int eg2 = base + R + lane - 16; if (eg2 >= E) eg2 = E - 1;
                dd[R + lane - 16] = ei[E + eg2];
            }
        }
        __syncwarp();

        float d[16][4];
#pragma unroll
        for (int t = 0; t < 16; ++t) { d[t][0] = d[t][1] = d[t][2] = d[t][3] = 0.f; }
        gemm_hl(sEAh, sEAl, sWTh, sWTl, R, lane, d, 4, PAD);

#pragma unroll
        for (int half = 0; half < 2; ++half) {
            int r   = R + qr + half * 8;
            int src = sd[r], dst = dd[r];
            const float2* bx = (const float2*)(g_xw1 + (size_t)src * DO);

            float sum = 0.f;
#pragma unroll
            for (int t = 0; t < 16; ++t) {
                float2 b = __ldg(bx + t * 4 + qc);
                float v0 = d[t][half * 2 + 0] + b.x;
                float v1 = d[t][half * 2 + 1] + b.y;
                v0 = v0 >= 0.f ? v0 : NEG_SLOPE * v0;
                v1 = v1 >= 0.f ? v1 : NEG_SLOPE * v1;
                d[t][half * 2 + 0] = v0;
                d[t][half * 2 + 1] = v1;
                sum += v0 + v1;
            }
            sum += __shfl_xor_sync(0xffffffffu, sum, 1);
            sum += __shfl_xor_sync(0xffffffffu, sum, 2);
            float mu = sum * (1.0f / DO);

            float vv = 0.f;
#pragma unroll
            for (int t = 0; t < 16; ++t) {
                float e0 = d[t][half * 2 + 0] - mu;
                float e1 = d[t][half * 2 + 1] - mu;
                vv += e0 * e0 + e1 * e1;
            }
            vv += __shfl_xor_sync(0xffffffffu, vv, 1);
            vv += __shfl_xor_sync(0xffffffffu, vv, 2);
            float inv = rsqrtf(vv * (1.0f / DO) + LN_EPS);

            if (base + r < E) {
                float* p = g_sums + (size_t)dst * DO;
#pragma unroll
                for (int t = 0; t < 16; ++t) {
                    float2 gv = g1f2[t * 4 + qc];
                    float2 bv = be1f2[t * 4 + qc];
                    float t0 = (d[t][half * 2 + 0] - mu) * inv * gv.x + bv.x;
                    float t1 = (d[t][half * 2 + 1] - mu) * inv * gv.y + bv.y;
                    asm volatile("red.global.add.v2.f32 [%0], {%1, %2};"
                                 :: "l"(p + t * 8 + qc * 2), "f"(t0), "f"(t1) : "memory");
                }
                if (qc == 0) atomicAdd(g_cnt + dst, 1.0f);
            }
        }
    }
}

// ---------------- kernel 4: fused node MLP via MMA (unchanged) -------------
__global__ void __launch_bounds__(256, 1) node_fused(
        const float* __restrict__ W2b,
        const float* __restrict__ g2,
        const float* __restrict__ be2,
        const float* __restrict__ b2b,
        float* __restrict__ out,
        int N) {
    extern __shared__ __align__(16) char smraw[];
    __nv_bfloat16* Th  = (__nv_bfloat16*)smraw;
    __nv_bfloat16* Tl  = Th  + 128 * PAD2;
    __nv_bfloat16* Wch = Tl  + 128 * PAD2;
    __nv_bfloat16* Wcl = Wch + 128 * PAD2;
    __nv_bfloat16* Wbh = Wcl + 128 * PAD2;
    __nv_bfloat16* Wbl = Wbh + 128 * PAD2;
    float* cs   = (float*)(Wbl + 128 * PAD2);
    float* c2s  = cs  + 128;
    float* g2s  = c2s + 128;
    float* be2s = g2s + 128;
    float* b2bs = be2s + 128;

    int tid = threadIdx.x;
    for (int idx = tid; idx < DO * DO; idx += 256) {
        int k = idx >> 7, o = idx & 127;
        float v = g_Wc[idx];
        __nv_bfloat16 h = __float2bfloat16(v);
        Wch[o * PAD2 + k] = h;
        Wcl[o * PAD2 + k] = __float2bfloat16(v - __bfloat162float(h));
        float w = W2b[idx];
        __nv_bfloat16 h2 = __float2bfloat16(w);
        Wbh[o * PAD2 + k] = h2;
        Wbl[o * PAD2 + k] = __float2bfloat16(w - __bfloat162float(h2));
    }
    if (tid < DO) {
        c2s [tid] = g_c2[tid];
        g2s [tid] = g2 [tid];
        be2s[tid] = be2[tid];
        b2bs[tid] = b2b[tid];
    }
    __syncthreads();

    uint32_t sTh  = (uint32_t)__cvta_generic_to_shared(Th);
    uint32_t sTl  = (uint32_t)__cvta_generic_to_shared(Tl);
    uint32_t sWch = (uint32_t)__cvta_generic_to_shared(Wch);
    uint32_t sWcl = (uint32_t)__cvta_generic_to_shared(Wcl);
    uint32_t sWbh = (uint32_t)__cvta_generic_to_shared(Wbh);
    uint32_t sWbl = (uint32_t)__cvta_generic_to_shared(Wbl);

    int warp = tid >> 5, lane = tid & 31;
    int R = warp * 16, qr = lane >> 2, qc = lane & 3;
    const float2* c2f2  = (const float2*)c2s;
    const float2* g2f2  = (const float2*)g2s;
    const float2* be2f2 = (const float2*)be2s;
    const float2* b2bf2 = (const float2*)b2bs;

    int srow = tid >> 1, skb = (tid & 1) * 64;
    int ntiles = (N + 127) >> 7;
    for (int tile = blockIdx.x; tile < ntiles; tile += gridDim.x) {
        int base = tile << 7;
        {
            int node = base + srow; if (node >= N) node = N - 1;
            float cn = g_cnt[node];
            float ic = cn > 0.f ? (1.0f / cn) : 0.f;
            if ((tid & 1) == 0) cs[srow] = cn;
            const float4* s = (const float4*)(g_sums + (size_t)node * DO + skb);
            ull* ph = (ull*)(Th + srow * PAD2 + skb);
            ull* pl = (ull*)(Tl + srow * PAD2 + skb);
#pragma unroll
            for (int j = 0; j < 16; ++j) {
                float4 v = s[j];
                v.x *= ic; v.y *= ic; v.z *= ic; v.w *= ic;
                f4_to_hl(v, ph[j], pl[j]);
            }
        }
        __syncwarp();

        float d[16][4];
#pragma unroll
        for (int t = 0; t < 16; ++t) d[t][0] = d[t][1] = d[t][2] = d[t][3] = 0.f;
        gemm_hl(sTh, sTl, sWch, sWcl, R, lane, d, 8, PAD2);
        __syncwarp();

#pragma unroll
        for (int half = 0; half < 2; ++half) {
            int r = R + qr + half * 8;
            int node = base + r; if (node >= N) node = N - 1;
            float cnr = cs[r];
            const float2* xw = (const float2*)(g_xw2 + (size_t)node * DO);

            float sum = 0.f;
#pragma unroll
            for (int t = 0; t < 16; ++t) {
                float2 b  = __ldg(xw + t * 4 + qc);
                float2 cv = c2f2[t * 4 + qc];
                float add0 = cnr > 0.f ? cv.x : 0.f;
                float add1 = cnr > 0.f ? cv.y : 0.f;
                float v0 = d[t][half * 2 + 0] + b.x + add0;
                float v1 = d[t][half * 2 + 1] + b.y + add1;
                v0 = v0 >= 0.f ? v0 : NEG_SLOPE * v0;
                v1 = v1 >= 0.f ? v1 : NEG_SLOPE * v1;
                d[t][half * 2 + 0] = v0;
                d[t][half * 2 + 1] = v1;
                sum += v0 + v1;
            }
            sum += __shfl_xor_sync(0xffffffffu, sum, 1);
            sum += __shfl_xor_sync(0xffffffffu, sum, 2);
            float mu = sum * (1.0f / DO);

            float vv = 0.f;
#pragma unroll
            for (int t = 0; t < 16; ++t) {
                float e0 = d[t][half * 2 + 0] - mu;
                float e1 = d[t][half * 2 + 1] - mu;
                vv += e0 * e0 + e1 * e1;
            }
            vv += __shfl_xor_sync(0xffffffffu, vv, 1);
            vv += __shfl_xor_sync(0xffffffffu, vv, 2);
            float inv = rsqrtf(vv * (1.0f / DO) + LN_EPS);

#pragma unroll
            for (int t = 0; t < 16; ++t) {
                float2 gv = g2f2[t * 4 + qc];
                float2 bv = be2f2[t * 4 + qc];
                float t0 = (d[t][half * 2 + 0] - mu) * inv * gv.x + bv.x;
                float t1 = (d[t][half * 2 + 1] - mu) * inv * gv.y + bv.y;
                __nv_bfloat16 h0 = __float2bfloat16(t0);
                __nv_bfloat16 h1 = __float2bfloat16(t1);
                int off = r * PAD2 + t * 8 + 2 * qc;
                *(uint32_t*)(Th + off) = bfpair(t0, t1);
                *(uint32_t*)(Tl + off) = bfpair(t0 - __bfloat162float(h0),
                                                t1 - __bfloat162float(h1));
            }
        }
        __syncwarp();

#pragma unroll
        for (int t = 0; t < 16; ++t) d[t][0] = d[t][1] = d[t][2] = d[t][3] = 0.f;
        gemm_hl(sTh, sTl, sWbh, sWbl, R, lane, d, 8, PAD2);

#pragma unroll
        for (int half = 0; half < 2; ++half) {
            int node = base + R + qr + half * 8;
            if (node < N) {
                float2* o = (float2*)(out + (size_t)node * DO);
#pragma unroll
                for (int t = 0; t < 16; ++t) {
                    float2 b = b2bf2[t * 4 + qc];
                    o[t * 4 + qc] = make_float2(d[t][half * 2] + b.x,
                                                d[t][half * 2 + 1] + b.y);
                }
            }
        }
        __syncwarp();
    }
}

// ---------------- launcher -------------------------------------------------
static bool g_attr_done = false;

extern "C" void kernel_launch(void* const* d_in, const int* in_sizes, int n_in,
                              void* d_out, int out_size) {
    const float* x   = (const float*)d_in[0];
    const int*   ei  = (const int*)  d_in[1];
    const float* ea  = (const float*)d_in[2];
    const float* u   = (const float*)d_in[3];
    const float* W1a = (const float*)d_in[5];
    const float* b1a = (const float*)d_in[6];
    const float* g1  = (const float*)d_in[7];
    const float* be1 = (const float*)d_in[8];
    const float* W1b = (const float*)d_in[9];
    const float* b1b = (const float*)d_in[10];
    const float* W2a = (const float*)d_in[11];
    const float* b2a = (const float*)d_in[12];
    const float* g2  = (const float*)d_in[13];
    const float* be2 = (const float*)d_in[14];
    const float* W2b = (const float*)d_in[15];
    const float* b2b = (const float*)d_in[16];
    float* out = (float*)d_out;

    int N = in_sizes[0] / DN;
    int E = in_sizes[2] / DE;

    const int PRE2_SMEM = 6 * 128 * PAD2 * 2 + 2 * 128 * 4;                // 209536
    const int EDGE_SMEM = 4 * 128 * PAD * 2 + 2 * 128 * 4 + 2 * 128 * 4;   // 75776
    const int NF_SMEM   = 6 * 128 * PAD2 * 2 + 5 * 128 * 4;                // 211456

    if (!g_attr_done) {
        cudaFuncSetAttribute(precompute_mma, cudaFuncAttributeMaxDynamicSharedMemorySize, PRE2_SMEM);
        cudaFuncSetAttribute(edge_kernel,    cudaFuncAttributeMaxDynamicSharedMemorySize, EDGE_SMEM);
        cudaFuncSetAttribute(node_fused,     cudaFuncAttributeMaxDynamicSharedMemorySize, NF_SMEM);
        g_attr_done = true;
    }

    c1_kernel<<<1, 128>>>(W1a, b1a, u);
    wc_kernel<<<129, 128>>>(W1b, b1b, W2a);
    precompute_mma<<<148, 256, PRE2_SMEM>>>(x, W1a, W2a, b2a, N);
    edge_kernel<<<296, 256, EDGE_SMEM>>>(ei, ea, W1a, g1, be1, E);
    node_fused<<<148, 256, NF_SMEM>>>(W2b, g2, be2, b2b, out, N);
}

// round 16
// speedup vs baseline: 1.1868x; 1.0179x over previous
#include <cuda_runtime.h>
#include <cuda_bf16.h>
#include <cstdint>

#define NEG_SLOPE 0.01f
#define LN_EPS    1e-5f

#define DN 128
#define DE 64
#define DG 32
#define DO 128
#define MAXN 50000
#define PAD 72         // bf16/row for K=64 tiles (edge)
#define PAD2 136       // bf16/row for K=128 tiles (node)

typedef unsigned long long ull;

// ---------------- scratch (device globals) ---------------------------------
__device__ __align__(16) float g_xw1 [MAXN * DO];   // x@Wx + c1 (edge bias)
__device__ __align__(16) float g_xw2 [MAXN * DO];   // x@W2a_x + b2a
__device__ __align__(16) float g_sums[MAXN * DO];
__device__ __align__(16) float g_cnt [MAXN];
__device__ __align__(16) float g_c1  [DO];
__device__ __align__(16) float g_Wc  [DO * DO];     // W1b @ W2a_agg
__device__ __align__(16) float g_c2  [DO];          // b1b @ W2a_agg

// ---------------- warp-MMA helpers (baseline PTX, sm_80+) ------------------
__device__ __forceinline__ void mma16816(
        float& d0, float& d1, float& d2, float& d3,
        uint32_t a0, uint32_t a1, uint32_t a2, uint32_t a3,
        uint32_t b0, uint32_t b1) {
    asm volatile(
        "mma.sync.aligned.m16n8k16.row.col.f32.bf16.bf16.f32 "
        "{%0,%1,%2,%3}, {%4,%5,%6,%7}, {%8,%9}, {%0,%1,%2,%3};"
        : "+f"(d0), "+f"(d1), "+f"(d2), "+f"(d3)
        : "r"(a0), "r"(a1), "r"(a2), "r"(a3), "r"(b0), "r"(b1));
}
__device__ __forceinline__ void ldsm_x4(
        uint32_t& r0, uint32_t& r1, uint32_t& r2, uint32_t& r3, uint32_t addr) {
    asm volatile("ldmatrix.sync.aligned.m8n8.x4.shared.b16 {%0,%1,%2,%3}, [%4];"
        : "=r"(r0), "=r"(r1), "=r"(r2), "=r"(r3) : "r"(addr));
}
__device__ __forceinline__ uint32_t bfpair(float a, float b) {
    __nv_bfloat162 t = __floats2bfloat162_rn(a, b);
    return *reinterpret_cast<uint32_t*>(&t);
}
__device__ __forceinline__ void f4_to_hl(float4 v, ull& ph, ull& pl) {
    __nv_bfloat16 h0 = __float2bfloat16(v.x), h1 = __float2bfloat16(v.y);
    __nv_bfloat16 h2 = __float2bfloat16(v.z), h3 = __float2bfloat16(v.w);
    uint32_t hA = bfpair(v.x, v.y), hB = bfpair(v.z, v.w);
    uint32_t lA = bfpair(v.x - __bfloat162float(h0), v.y - __bfloat162float(h1));
    uint32_t lB = bfpair(v.z - __bfloat162float(h2), v.w - __bfloat162float(h3));
    ph = (ull)hA | ((ull)hB << 32);
    pl = (ull)lA | ((ull)lB << 32);
}

// D[16x128] per warp += A(hi/lo) @ B(hi/lo)^T via ldmatrix fragments.
__device__ __forceinline__ void gemm_hl(
        uint32_t sAh, uint32_t sAl, uint32_t sBh, uint32_t sBl,
        int R, int lane, float d[16][4], int ksteps, int pad) {
    uint32_t aoff = ((R + (lane & 15)) * pad + ((lane >> 4) << 3)) * 2;
    int m = lane >> 3;
    uint32_t boff = (((m >> 1) * 8 + (lane & 7)) * pad + ((m & 1) << 3)) * 2;
#pragma unroll
    for (int ks = 0; ks < 8; ++ks) {
        if (ks >= ksteps) break;
        uint32_t ka = (uint32_t)(ks * 16 * 2);
        uint32_t ah0, ah1, ah2, ah3, al0, al1, al2, al3;
        ldsm_x4(ah0, ah1, ah2, ah3, sAh + aoff + ka);
        ldsm_x4(al0, al1, al2, al3, sAl + aoff + ka);
#pragma unroll
        for (int tt = 0; tt < 8; ++tt) {
            uint32_t bo = boff + (uint32_t)(tt * 16 * pad * 2) + ka;
            uint32_t bh0, bh1, bh2, bh3, bl0, bl1, bl2, bl3;
            ldsm_x4(bh0, bh1, bh2, bh3, sBh + bo);
            ldsm_x4(bl0, bl1, bl2, bl3, sBl + bo);
            int t0 = 2 * tt, t1 = 2 * tt + 1;
            mma16816(d[t0][0], d[t0][1], d[t0][2], d[t0][3], ah0, ah1, ah2, ah3, bh0, bh1);
            mma16816(d[t0][0], d[t0][1], d[t0][2], d[t0][3], al0, al1, al2, al3, bh0, bh1);
            mma16816(d[t0][0], d[t0][1], d[t0][2], d[t0][3], ah0, ah1, ah2, ah3, bl0, bl1);
            mma16816(d[t1][0], d[t1][1], d[t1][2], d[t1][3], ah0, ah1, ah2, ah3, bh2, bh3);
            mma16816(d[t1][0], d[t1][1], d[t1][2], d[t1][3], al0, al1, al2, al3, bh2, bh3);
            mma16816(d[t1][0], d[t1][1], d[t1][2], d[t1][3], ah0, ah1, ah2, ah3, bl2, bl3);
        }
    }
}

// ---------------- kernel 0: c1 = u @ Wu + b1a ------------------------------
__global__ void c1_kernel(const float* __restrict__ W1a,
                          const float* __restrict__ b1a,
                          const float* __restrict__ u) {
    int j = threadIdx.x;
    float acc = b1a[j];
#pragma unroll
    for (int k = 0; k < DG; ++k)
        acc += u[k] * W1a[(DN + DE + k) * DO + j];
    g_c1[j] = acc;
}

// ---------------- kernel W: Wc = W1b @ W2a_agg ; c2 = b1b @ W2a_agg --------
__global__ void wc_kernel(const float* __restrict__ W1b,
                          const float* __restrict__ b1b,
                          const float* __restrict__ W2a) {
    __shared__ float row[DO];
    int j = threadIdx.x;
    int i = blockIdx.x;
    row[j] = (i < DO) ? W1b[i * DO + j] : b1b[j];
    __syncthreads();
    float acc = 0.f;
#pragma unroll 8
    for (int k = 0; k < DO; ++k)
        acc += row[k] * W2a[(DN + k) * DO + j];
    if (i < DO) g_Wc[i * DO + j] = acc;
    else        g_c2[j] = acc;
}

// ---------------- kernel 2: precompute via MMA + scatter-buffer zeroing ----
__global__ void __launch_bounds__(256, 1) precompute_mma(
        const float* __restrict__ x,
        const float* __restrict__ W1a,
        const float* __restrict__ W2a,
        const float* __restrict__ b2a,
        int N) {
    extern __shared__ __align__(16) char smraw[];
    __nv_bfloat16* Xh  = (__nv_bfloat16*)smraw;
    __nv_bfloat16* Xl  = Xh  + 128 * PAD2;
    __nv_bfloat16* Wxh = Xl  + 128 * PAD2;
    __nv_bfloat16* Wxl = Wxh + 128 * PAD2;
    __nv_bfloat16* W2h = Wxl + 128 * PAD2;
    __nv_bfloat16* W2l = W2h + 128 * PAD2;
    float* b2as = (float*)(W2l + 128 * PAD2);
    float* c1s  = b2as + DO;

    int tid = threadIdx.x;

    // ---- zero scatter buffers ----
    {
        int gid = blockIdx.x * blockDim.x + tid;
        int gth = gridDim.x * blockDim.x;
        float4 z = make_float4(0.f, 0.f, 0.f, 0.f);
        int nq = N * DO / 4;
        for (int i = gid; i < nq; i += gth) ((float4*)g_sums)[i] = z;
        for (int i = gid; i < N;  i += gth) g_cnt[i] = 0.f;
    }

    for (int idx = tid; idx < DO * DN; idx += 256) {
        int k = idx >> 7, o = idx & 127;
        float v = W1a[idx];
        __nv_bfloat16 h = __float2bfloat16(v);
        Wxh[o * PAD2 + k] = h;
        Wxl[o * PAD2 + k] = __float2bfloat16(v - __bfloat162float(h));
        float w = W2a[idx];
        __nv_bfloat16 h2 = __float2bfloat16(w);
        W2h[o * PAD2 + k] = h2;
        W2l[o * PAD2 + k] = __float2bfloat16(w - __bfloat162float(h2));
    }
    if (tid < DO) {
        b2as[tid] = b2a[tid];
        c1s [tid] = g_c1[tid];
    }
    __syncthreads();

    uint32_t sXh  = (uint32_t)__cvta_generic_to_shared(Xh);
    uint32_t sXl  = (uint32_t)__cvta_generic_to_shared(Xl);
    uint32_t sWxh = (uint32_t)__cvta_generic_to_shared(Wxh);
    uint32_t sWxl = (uint32_t)__cvta_generic_to_shared(Wxl);
    uint32_t sW2h = (uint32_t)__cvta_generic_to_shared(W2h);
    uint32_t sW2l = (uint32_t)__cvta_generic_to_shared(W2l);

    int warp = tid >> 5, lane = tid & 31;
    int R = warp * 16, qr = lane >> 2, qc = lane & 3;
    const float2* b2f2 = (const float2*)b2as;
    const float2* c1f2 = (const float2*)c1s;

    int srow = tid >> 1, skb = (tid & 1) * 64;
    int ntiles = (N + 127) >> 7;
    for (int tile = blockIdx.x; tile < ntiles; tile += gridDim.x) {
        int base = tile << 7;
        {
            int node = base + srow; if (node >= N) node = N - 1;
            const float4* s = (const float4*)(x + (size_t)node * DN + skb);
            ull* ph = (ull*)(Xh + srow * PAD2 + skb);
            ull* pl = (ull*)(Xl + srow * PAD2 + skb);
#pragma unroll
            for (int j = 0; j < 16; ++j) f4_to_hl(s[j], ph[j], pl[j]);
        }
        __syncwarp();

        float d[16][4];
#pragma unroll
        for (int t = 0; t < 16; ++t) d[t][0] = d[t][1] = d[t][2] = d[t][3] = 0.f;
        gemm_hl(sXh, sXl, sWxh, sWxl, R, lane, d, 8, PAD2);
#pragma unroll
        for (int half = 0; half < 2; ++half) {
            int node = base + R + qr + half * 8;
            if (node < N) {
                float2* o = (float2*)(g_xw1 + (size_t)node * DO);
#pragma unroll
                for (int t = 0; t < 16; ++t) {
                    float2 cv = c1f2[t * 4 + qc];
                    o[t * 4 + qc] = make_float2(d[t][half * 2] + cv.x,
                                                d[t][half * 2 + 1] + cv.y);
                }
            }
        }
#pragma unroll
        for (int t = 0; t < 16; ++t) d[t][0] = d[t][1] = d[t][2] = d[t][3] = 0.f;
        gemm_hl(sXh, sXl, sW2h, sW2l, R, lane, d, 8, PAD2);
#pragma unroll
        for (int half = 0; half < 2; ++half) {
            int node = base + R + qr + half * 8;
            if (node < N) {
                float2* o = (float2*)(g_xw2 + (size_t)node * DO);
#pragma unroll
                for (int t = 0; t < 16; ++t) {
                    float2 b = b2f2[t * 4 + qc];
                    o[t * 4 + qc] = make_float2(d[t][half * 2] + b.x,
                                                d[t][half * 2 + 1] + b.y);
                }
            }
        }
        __syncwarp();
    }
}

// ---------------- kernel 3: edge phase (32 edges/warp, 256-edge tiles) -----
// Each warp owns edges [R2, R2+32) of the tile: two accumulator groups.
// B fragments loaded once per (kstep,tt) and applied to both groups.
__global__ void __launch_bounds__(256, 1) edge_kernel(
        const int*   __restrict__ ei,
        const float* __restrict__ ea,
        const float* __restrict__ W1a,
        const float* __restrict__ g1,
        const float* __restrict__ be1,
        int E) {
    extern __shared__ __align__(16) char smraw[];
    __nv_bfloat16* EAh = (__nv_bfloat16*)smraw;        // 256*PAD
    __nv_bfloat16* EAl = EAh + 256 * PAD;
    __nv_bfloat16* WTh = EAl + 256 * PAD;              // 128*PAD
    __nv_bfloat16* WTl = WTh + 128 * PAD;
    float* g1s  = (float*)(WTl + 128 * PAD);
    float* be1s = g1s + 128;
    int*   sd   = (int*)(be1s + 128);                  // 256
    int*   dd   = sd + 256;

    int tid = threadIdx.x;
    for (int idx = tid; idx < DE * DO; idx += 256) {
        int k = idx >> 7, o = idx & 127;
        float v = W1a[(DN + k) * DO + o];
        __nv_bfloat16 h = __float2bfloat16(v);
        WTh[o * PAD + k] = h;
        WTl[o * PAD + k] = __float2bfloat16(v - __bfloat162float(h));
    }
    if (tid < 128) {
        g1s [tid] = g1 [tid];
        be1s[tid] = be1[tid];
    }
    __syncthreads();   // weights + LN vectors visible (once)

    uint32_t sEAh = (uint32_t)__cvta_generic_to_shared(EAh);
    uint32_t sEAl = (uint32_t)__cvta_generic_to_shared(EAl);
    uint32_t sWTh = (uint32_t)__cvta_generic_to_shared(WTh);
    uint32_t sWTl = (uint32_t)__cvta_generic_to_shared(WTl);

    int warp = tid >> 5, lane = tid & 31;
    int R2 = warp * 32;                       // first edge row of this warp
    int qr = lane >> 2, qc = lane & 3;

    const float2* g1f2  = (const float2*)g1s;
    const float2* be1f2 = (const float2*)be1s;

    // fragment addresses
    uint32_t aoff0 = (uint32_t)(((R2 + (lane & 15)) * PAD + ((lane >> 4) << 3)) * 2);
    uint32_t aoff1 = aoff0 + (uint32_t)(16 * PAD * 2);
    int m = lane >> 3;
    uint32_t boff = (uint32_t)((((m >> 1) * 8 + (lane & 7)) * PAD + ((m & 1) << 3)) * 2);

    // staging geometry: pass p -> edge R2 + p*16 + (lane>>1), k-half (lane&1)*32
    int kb = (lane & 1) * 32;

    int ntiles = (E + 255) >> 8;
    for (int tile = blockIdx.x; tile < ntiles; tile += gridDim.x) {
        int base = tile << 8;
        __syncwarp();   // own warp's prior-tile smem reads done

        // ---- stage own 32 EA rows + own sd/dd (warp-private) ----
#pragma unroll
        for (int p = 0; p < 2; ++p) {
            int e_loc = R2 + p * 16 + (lane >> 1);
            int eg = base + e_loc; if (eg >= E) eg = E - 1;
            const float4* s = (const float4*)(ea + (size_t)eg * DE + kb);
            ull* ph = (ull*)(EAh + e_loc * PAD + kb);
            ull* pl = (ull*)(EAl + e_loc * PAD + kb);
#pragma unroll
            for (int j = 0; j < 8; ++j) f4_to_hl(s[j], ph[j], pl[j]);
        }
        {
            int eg2 = base + R2 + lane; if (eg2 >= E) eg2 = E - 1;
            sd[R2 + lane] = ei[eg2];
            dd[R2 + lane] = ei[E + eg2];
        }
        __syncwarp();

        // ---- MMA: 2 groups x 16x128, B loaded once per (ks,tt) ----
        float d0[16][4], d1[16][4];
#pragma unroll
        for (int t = 0; t < 16; ++t) {
            d0[t][0] = d0[t][1] = d0[t][2] = d0[t][3] = 0.f;
            d1[t][0] = d1[t][1] = d1[t][2] = d1[t][3] = 0.f;
        }
#pragma unroll
        for (int ks = 0; ks < 4; ++ks) {
            uint32_t ka = (uint32_t)(ks * 16 * 2);
            uint32_t a0h0, a0h1, a0h2, a0h3, a0l0, a0l1, a0l2, a0l3;
            uint32_t a1h0, a1h1, a1h2, a1h3, a1l0, a1l1, a1l2, a1l3;
            ldsm_x4(a0h0, a0h1, a0h2, a0h3, sEAh + aoff0 + ka);
            ldsm_x4(a0l0, a0l1, a0l2, a0l3, sEAl + aoff0 + ka);
            ldsm_x4(a1h0, a1h1, a1h2, a1h3, sEAh + aoff1 + ka);
            ldsm_x4(a1l0, a1l1, a1l2, a1l3, sEAl + aoff1 + ka);
#pragma unroll
            for (int tt = 0; tt < 8; ++tt) {
                uint32_t bo = boff + (uint32_t)(tt * 16 * PAD * 2) + ka;
                uint32_t bh0, bh1, bh2, bh3, bl0, bl1, bl2, bl3;
                ldsm_x4(bh0, bh1, bh2, bh3, sWTh + bo);
                ldsm_x4(bl0, bl1, bl2, bl3, sWTl + bo);
                int t0 = 2 * tt, t1 = 2 * tt + 1;
                mma16816(d0[t0][0], d0[t0][1], d0[t0][2], d0[t0][3], a0h0, a0h1, a0h2, a0h3, bh0, bh1);
                mma16816(d0[t0][0], d0[t0][1], d0[t0][2], d0[t0][3], a0l0, a0l1, a0l2, a0l3, bh0, bh1);
                mma16816(d0[t0][0], d0[t0][1], d0[t0][2], d0[t0][3], a0h0, a0h1, a0h2, a0h3, bl0, bl1);
                mma16816(d0[t1][0], d0[t1][1], d0[t1][2], d0[t1][3], a0h0, a0h1, a0h2, a0h3, bh2, bh3);
                mma16816(d0[t1][0], d0[t1][1], d0[t1][2], d0[t1][3], a0l0, a0l1, a0l2, a0l3, bh2, bh3);
                mma16816(d0[t1][0], d0[t1][1], d0[t1][2], d0[t1][3], a0h0, a0h1, a0h2, a0h3, bl2, bl3);
                mma16816(d1[t0][0], d1[t0][1], d1[t0][2], d1[t0][3], a1h0, a1h1, a1h2, a1h3, bh0, bh1);
                mma16816(d1[t0][0], d1[t0][1], d1[t0][2], d1[t0][3], a1l0, a1l1, a1l2, a1l3, bh0, bh1);
                mma16816(d1[t0][0], d1[t0][1], d1[t0][2], d1[t0][3], a1h0, a1h1, a1h2, a1h3, bl0, bl1);
                mma16816(d1[t1][0], d1[t1][1], d1[t1][2], d1[t1][3], a1h0, a1h1, a1h2, a1h3, bh2, bh3);
                mma16816(d1[t1][0], d1[t1][1], d1[t1][2], d1[t1][3], a1l0, a1l1, a1l2, a1l3, bh2, bh3);
                mma16816(d1[t1][0], d1[t1][1], d1[t1][2], d1[t1][3], a1h0, a1h1, a1h2, a1h3, bl2, bl3);
            }
        }

        // ---- epilogue: 4 edge rows per lane (2 groups x 2 halves) ----
#pragma unroll
        for (int g = 0; g < 2; ++g) {
            float (*d)[4] = g ? d1 : d0;
#pragma unroll
            for (int half = 0; half < 2; ++half) {
                int r   = R2 + g * 16 + qr + half * 8;
                int src = sd[r], dst = dd[r];
                const float2* bx = (const float2*)(g_xw1 + (size_t)src * DO);

                float sum = 0.f;
#pragma unroll
                for (int t = 0; t < 16; ++t) {
                    float2 b = __ldg(bx + t * 4 + qc);
                    float v0 = d[t][half * 2 + 0] + b.x;
                    float v1 = d[t][half * 2 + 1] + b.y;
                    v0 = v0 >= 0.f ? v0 : NEG_SLOPE * v0;
                    v1 = v1 >= 0.f ? v1 : NEG_SLOPE * v1;
                    d[t][half * 2 + 0] = v0;
                    d[t][half * 2 + 1] = v1;
                    sum += v0 + v1;
                }
                sum += __shfl_xor_sync(0xffffffffu, sum, 1);
                sum += __shfl_xor_sync(0xffffffffu, sum, 2);
                float mu = sum * (1.0f / DO);

                float vv = 0.f;
#pragma unroll
                for (int t = 0; t < 16; ++t) {
                    float e0 = d[t][half * 2 + 0] - mu;
                    float e1 = d[t][half * 2 + 1] - mu;
                    vv += e0 * e0 + e1 * e1;
                }
                vv += __shfl_xor_sync(0xffffffffu, vv, 1);
                vv += __shfl_xor_sync(0xffffffffu, vv, 2);
                float inv = rsqrtf(vv * (1.0f / DO) + LN_EPS);

                if (base + r < E) {
                    float* p = g_sums + (size_t)dst * DO;
#pragma unroll
                    for (int t = 0; t < 16; ++t) {
                        float2 gv = g1f2[t * 4 + qc];
                        float2 bv = be1f2[t * 4 + qc];
                        float t0 = (d[t][half * 2 + 0] - mu) * inv * gv.x + bv.x;
                        float t1 = (d[t][half * 2 + 1] - mu) * inv * gv.y + bv.y;
                        asm volatile("red.global.add.v2.f32 [%0], {%1, %2};"
                                     :: "l"(p + t * 8 + qc * 2), "f"(t0), "f"(t1) : "memory");
                    }
                    if (qc == 0) atomicAdd(g_cnt + dst, 1.0f);
                }
            }
        }
    }
}

// ---------------- kernel 4: fused node MLP via MMA (unchanged) -------------
__global__ void __launch_bounds__(256, 1) node_fused(
        const float* __restrict__ W2b,
        const float* __restrict__ g2,
        const float* __restrict__ be2,
        const float* __restrict__ b2b,
        float* __restrict__ out,
        int N) {
    extern __shared__ __align__(16) char smraw[];
    __nv_bfloat16* Th  = (__nv_bfloat16*)smraw;
    __nv_bfloat16* Tl  = Th  + 128 * PAD2;
    __nv_bfloat16* Wch = Tl  + 128 * PAD2;
    __nv_bfloat16* Wcl = Wch + 128 * PAD2;
    __nv_bfloat16* Wbh = Wcl + 128 * PAD2;
    __nv_bfloat16* Wbl = Wbh + 128 * PAD2;
    float* cs   = (float*)(Wbl + 128 * PAD2);
    float* c2s  = cs  + 128;
    float* g2s  = c2s + 128;
    float* be2s = g2s + 128;
    float* b2bs = be2s + 128;

    int tid = threadIdx.x;
    for (int idx = tid; idx < DO * DO; idx += 256) {
        int k = idx >> 7, o = idx & 127;
        float v = g_Wc[idx];
        __nv_bfloat16 h = __float2bfloat16(v);
        Wch[o * PAD2 + k] = h;
        Wcl[o * PAD2 + k] = __float2bfloat16(v - __bfloat162float(h));
        float w = W2b[idx];
        __nv_bfloat16 h2 = __float2bfloat16(w);
        Wbh[o * PAD2 + k] = h2;
        Wbl[o * PAD2 + k] = __float2bfloat16(w - __bfloat162float(h2));
    }
    if (tid < DO) {
        c2s [tid] = g_c2[tid];
        g2s [tid] = g2 [tid];
        be2s[tid] = be2[tid];
        b2bs[tid] = b2b[tid];
    }
    __syncthreads();

    uint32_t sTh  = (uint32_t)__cvta_generic_to_shared(Th);
    uint32_t sTl  = (uint32_t)__cvta_generic_to_shared(Tl);
    uint32_t sWch = (uint32_t)__cvta_generic_to_shared(Wch);
    uint32_t sWcl = (uint32_t)__cvta_generic_to_shared(Wcl);
    uint32_t sWbh = (uint32_t)__cvta_generic_to_shared(Wbh);
    uint32_t sWbl = (uint32_t)__cvta_generic_to_shared(Wbl);

    int warp = tid >> 5, lane = tid & 31;
    int R = warp * 16, qr = lane >> 2, qc = lane & 3;
    const float2* c2f2  = (const float2*)c2s;
    const float2* g2f2  = (const float2*)g2s;
    const float2* be2f2 = (const float2*)be2s;
    const float2* b2bf2 = (const float2*)b2bs;

    int srow = tid >> 1, skb = (tid & 1) * 64;
    int ntiles = (N + 127) >> 7;
    for (int tile = blockIdx.x; tile < ntiles; tile += gridDim.x) {
        int base = tile << 7;
        {
            int node = base + srow; if (node >= N) node = N - 1;
            float cn = g_cnt[node];
            float ic = cn > 0.f ? (1.0f / cn) : 0.f;
            if ((tid & 1) == 0) cs[srow] = cn;
            const float4* s = (const float4*)(g_sums + (size_t)node * DO + skb);
            ull* ph = (ull*)(Th + srow * PAD2 + skb);
            ull* pl = (ull*)(Tl + srow * PAD2 + skb);
#pragma unroll
            for (int j = 0; j < 16; ++j) {
                float4 v = s[j];
                v.x *= ic; v.y *= ic; v.z *= ic; v.w *= ic;
                f4_to_hl(v, ph[j], pl[j]);
            }
        }
        __syncwarp();

        float d[16][4];
#pragma unroll
        for (int t = 0; t < 16; ++t) d[t][0] = d[t][1] = d[t][2] = d[t][3] = 0.f;
        gemm_hl(sTh, sTl, sWch, sWcl, R, lane, d, 8, PAD2);
        __syncwarp();

#pragma unroll
        for (int half = 0; half < 2; ++half) {
            int r = R + qr + half * 8;
            int node = base + r; if (node >= N) node = N - 1;
            float cnr = cs[r];
            const float2* xw = (const float2*)(g_xw2 + (size_t)node * DO);

            float sum = 0.f;
#pragma unroll
            for (int t = 0; t < 16; ++t) {
                float2 b  = __ldg(xw + t * 4 + qc);
                float2 cv = c2f2[t * 4 + qc];
                float add0 = cnr > 0.f ? cv.x : 0.f;
                float add1 = cnr > 0.f ? cv.y : 0.f;
                float v0 = d[t][half * 2 + 0] + b.x + add0;
                float v1 = d[t][half * 2 + 1] + b.y + add1;
                v0 = v0 >= 0.f ? v0 : NEG_SLOPE * v0;
                v1 = v1 >= 0.f ? v1 : NEG_SLOPE * v1;
                d[t][half * 2 + 0] = v0;
                d[t][half * 2 + 1] = v1;
                sum += v0 + v1;
            }
            sum += __shfl_xor_sync(0xffffffffu, sum, 1);
            sum += __shfl_xor_sync(0xffffffffu, sum, 2);
            float mu = sum * (1.0f / DO);

            float vv = 0.f;
#pragma unroll
            for (int t = 0; t < 16; ++t) {
                float e0 = d[t][half * 2 + 0] - mu;
                float e1 = d[t][half * 2 + 1] - mu;
                vv += e0 * e0 + e1 * e1;
            }
            vv += __shfl_xor_sync(0xffffffffu, vv, 1);
            vv += __shfl_xor_sync(0xffffffffu, vv, 2);
            float inv = rsqrtf(vv * (1.0f / DO) + LN_EPS);

#pragma unroll
            for (int t = 0; t < 16; ++t) {
                float2 gv = g2f2[t * 4 + qc];
                float2 bv = be2f2[t * 4 + qc];
                float t0 = (d[t][half * 2 + 0] - mu) * inv * gv.x + bv.x;
                float t1 = (d[t][half * 2 + 1] - mu) * inv * gv.y + bv.y;
                __nv_bfloat16 h0 = __float2bfloat16(t0);
                __nv_bfloat16 h1 = __float2bfloat16(t1);
                int off = r * PAD2 + t * 8 + 2 * qc;
                *(uint32_t*)(Th + off) = bfpair(t0, t1);
                *(uint32_t*)(Tl + off) = bfpair(t0 - __bfloat162float(h0),
                                                t1 - __bfloat162float(h1));
            }
        }
        __syncwarp();

#pragma unroll
        for (int t = 0; t < 16; ++t) d[t][0] = d[t][1] = d[t][2] = d[t][3] = 0.f;
        gemm_hl(sTh, sTl, sWbh, sWbl, R, lane, d, 8, PAD2);

#pragma unroll
        for (int half = 0; half < 2; ++half) {
            int node = base + R + qr + half * 8;
            if (node < N) {
                float2* o = (float2*)(out + (size_t)node * DO);
#pragma unroll
                for (int t = 0; t < 16; ++t) {
                    float2 b = b2bf2[t * 4 + qc];
                    o[t * 4 + qc] = make_float2(d[t][half * 2] + b.x,
                                                d[t][half * 2 + 1] + b.y);
                }
            }
        }
        __syncwarp();
    }
}

// ---------------- launcher -------------------------------------------------
static bool g_attr_done = false;

extern "C" void kernel_launch(void* const* d_in, const int* in_sizes, int n_in,
                              void* d_out, int out_size) {
    const float* x   = (const float*)d_in[0];
    const int*   ei  = (const int*)  d_in[1];
    const float* ea  = (const float*)d_in[2];
    const float* u   = (const float*)d_in[3];
    const float* W1a = (const float*)d_in[5];
    const float* b1a = (const float*)d_in[6];
    const float* g1  = (const float*)d_in[7];
    const float* be1 = (const float*)d_in[8];
    const float* W1b = (const float*)d_in[9];
    const float* b1b = (const float*)d_in[10];
    const float* W2a = (const float*)d_in[11];
    const float* b2a = (const float*)d_in[12];
    const float* g2  = (const float*)d_in[13];
    const float* be2 = (const float*)d_in[14];
    const float* W2b = (const float*)d_in[15];
    const float* b2b = (const float*)d_in[16];
    float* out = (float*)d_out;

    int N = in_sizes[0] / DN;
    int E = in_sizes[2] / DE;

    const int PRE2_SMEM = 6 * 128 * PAD2 * 2 + 2 * 128 * 4;                        // 209536
    const int EDGE_SMEM = (256 + 128) * PAD * 2 * 2 + 2 * 128 * 4 + 2 * 256 * 4;   // 113664
    const int NF_SMEM   = 6 * 128 * PAD2 * 2 + 5 * 128 * 4;                        // 211456

    if (!g_attr_done) {
        cudaFuncSetAttribute(precompute_mma, cudaFuncAttributeMaxDynamicSharedMemorySize, PRE2_SMEM);
        cudaFuncSetAttribute(edge_kernel,    cudaFuncAttributeMaxDynamicSharedMemorySize, EDGE_SMEM);
        cudaFuncSetAttribute(node_fused,     cudaFuncAttributeMaxDynamicSharedMemorySize, NF_SMEM);
        g_attr_done = true;
    }

    c1_kernel<<<1, 128>>>(W1a, b1a, u);
    wc_kernel<<<129, 128>>>(W1b, b1b, W2a);
    precompute_mma<<<148, 256, PRE2_SMEM>>>(x, W1a, W2a, b2a, N);
    edge_kernel<<<148, 256, EDGE_SMEM>>>(ei, ea, W1a, g1, be1, E);
    node_fused<<<148, 256, NF_SMEM>>>(W2b, g2, be2, b2b, out, N);
}

// round 17
// speedup vs baseline: 1.2608x; 1.0623x over previous
#include <cuda_runtime.h>
#include <cuda_bf16.h>
#include <cuda_fp16.h>
#include <cstdint>

#define NEG_SLOPE 0.01f
#define LN_EPS    1e-5f

#define DN 128
#define DE 64
#define DG 32
#define DO 128
#define MAXN 50000
#define PAD 72         // b16 elems/row for K=64 tiles (edge)
#define PAD2 136       // b16 elems/row for K=128 tiles (node)

typedef unsigned long long ull;

// ---------------- scratch (device globals) ---------------------------------
__device__ __align__(16) float g_xw1 [MAXN * DO];   // x@Wx + c1 (edge bias)
__device__ __align__(16) float g_xw2 [MAXN * DO];   // x@W2a_x + b2a
__device__ __align__(16) float g_sums[MAXN * DO];
__device__ __align__(16) float g_cnt [MAXN];
__device__ __align__(16) float g_Wc  [DO * DO];     // W1b @ W2a_agg
__device__ __align__(16) float g_c2  [DO];          // b1b @ W2a_agg

// ---------------- warp-MMA helpers (baseline PTX, sm_80+) ------------------
__device__ __forceinline__ void mma16816(
        float& d0, float& d1, float& d2, float& d3,
        uint32_t a0, uint32_t a1, uint32_t a2, uint32_t a3,
        uint32_t b0, uint32_t b1) {
    asm volatile(
        "mma.sync.aligned.m16n8k16.row.col.f32.bf16.bf16.f32 "
        "{%0,%1,%2,%3}, {%4,%5,%6,%7}, {%8,%9}, {%0,%1,%2,%3};"
        : "+f"(d0), "+f"(d1), "+f"(d2), "+f"(d3)
        : "r"(a0), "r"(a1), "r"(a2), "r"(a3), "r"(b0), "r"(b1));
}
__device__ __forceinline__ void mma16816h(
        float& d0, float& d1, float& d2, float& d3,
        uint32_t a0, uint32_t a1, uint32_t a2, uint32_t a3,
        uint32_t b0, uint32_t b1) {
    asm volatile(
        "mma.sync.aligned.m16n8k16.row.col.f32.f16.f16.f32 "
        "{%0,%1,%2,%3}, {%4,%5,%6,%7}, {%8,%9}, {%0,%1,%2,%3};"
        : "+f"(d0), "+f"(d1), "+f"(d2), "+f"(d3)
        : "r"(a0), "r"(a1), "r"(a2), "r"(a3), "r"(b0), "r"(b1));
}
__device__ __forceinline__ void ldsm_x4(
        uint32_t& r0, uint32_t& r1, uint32_t& r2, uint32_t& r3, uint32_t addr) {
    asm volatile("ldmatrix.sync.aligned.m8n8.x4.shared.b16 {%0,%1,%2,%3}, [%4];"
        : "=r"(r0), "=r"(r1), "=r"(r2), "=r"(r3) : "r"(addr));
}
__device__ __forceinline__ uint32_t bfpair(float a, float b) {
    __nv_bfloat162 t = __floats2bfloat162_rn(a, b);
    return *reinterpret_cast<uint32_t*>(&t);
}
__device__ __forceinline__ uint32_t hpair(float a, float b) {
    __half2 t = __floats2half2_rn(a, b);
    return *reinterpret_cast<uint32_t*>(&t);
}
__device__ __forceinline__ void f4_to_hl(float4 v, ull& ph, ull& pl) {
    __nv_bfloat16 h0 = __float2bfloat16(v.x), h1 = __float2bfloat16(v.y);
    __nv_bfloat16 h2 = __float2bfloat16(v.z), h3 = __float2bfloat16(v.w);
    uint32_t hA = bfpair(v.x, v.y), hB = bfpair(v.z, v.w);
    uint32_t lA = bfpair(v.x - __bfloat162float(h0), v.y - __bfloat162float(h1));
    uint32_t lB = bfpair(v.z - __bfloat162float(h2), v.w - __bfloat162float(h3));
    ph = (ull)hA | ((ull)hB << 32);
    pl = (ull)lA | ((ull)lB << 32);
}
__device__ __forceinline__ void f4_to_hl_h(float4 v, ull& ph, ull& pl) {
    __half h0 = __float2half(v.x), h1 = __float2half(v.y);
    __half h2 = __float2half(v.z), h3 = __float2half(v.w);
    uint32_t hA = hpair(v.x, v.y), hB = hpair(v.z, v.w);
    uint32_t lA = hpair(v.x - __half2float(h0), v.y - __half2float(h1));
    uint32_t lB = hpair(v.z - __half2float(h2), v.w - __half2float(h3));
    ph = (ull)hA | ((ull)hB << 32);
    pl = (ull)lA | ((ull)lB << 32);
}

// D[16x128] per warp += A(hi/lo) @ B(hi/lo)^T via ldmatrix fragments (bf16).
__device__ __forceinline__ void gemm_hl(
        uint32_t sAh, uint32_t sAl, uint32_t sBh, uint32_t sBl,
        int R, int lane, float d[16][4], int ksteps, int pad) {
    uint32_t aoff = ((R + (lane & 15)) * pad + ((lane >> 4) << 3)) * 2;
    int m = lane >> 3;
    uint32_t boff = (((m >> 1) * 8 + (lane & 7)) * pad + ((m & 1) << 3)) * 2;
#pragma unroll
    for (int ks = 0; ks < 8; ++ks) {
        if (ks >= ksteps) break;
        uint32_t ka = (uint32_t)(ks * 16 * 2);
        uint32_t ah0, ah1, ah2, ah3, al0, al1, al2, al3;
        ldsm_x4(ah0, ah1, ah2, ah3, sAh + aoff + ka);
        ldsm_x4(al0, al1, al2, al3, sAl + aoff + ka);
#pragma unroll
        for (int tt = 0; tt < 8; ++tt) {
            uint32_t bo = boff + (uint32_t)(tt * 16 * pad * 2) + ka;
            uint32_t bh0, bh1, bh2, bh3, bl0, bl1, bl2, bl3;
            ldsm_x4(bh0, bh1, bh2, bh3, sBh + bo);
            ldsm_x4(bl0, bl1, bl2, bl3, sBl + bo);
            int t0 = 2 * tt, t1 = 2 * tt + 1;
            mma16816(d[t0][0], d[t0][1], d[t0][2], d[t0][3], ah0, ah1, ah2, ah3, bh0, bh1);
            mma16816(d[t0][0], d[t0][1], d[t0][2], d[t0][3], al0, al1, al2, al3, bh0, bh1);
            mma16816(d[t0][0], d[t0][1], d[t0][2], d[t0][3], ah0, ah1, ah2, ah3, bl0, bl1);
            mma16816(d[t1][0], d[t1][1], d[t1][2], d[t1][3], ah0, ah1, ah2, ah3, bh2, bh3);
            mma16816(d[t1][0], d[t1][1], d[t1][2], d[t1][3], al0, al1, al2, al3, bh2, bh3);
            mma16816(d[t1][0], d[t1][1], d[t1][2], d[t1][3], ah0, ah1, ah2, ah3, bl2, bl3);
        }
    }
}

// ---------------- kernel W: Wc = W1b @ W2a_agg ; c2 = b1b @ W2a_agg --------
__global__ void wc_kernel(const float* __restrict__ W1b,
                          const float* __restrict__ b1b,
                          const float* __restrict__ W2a) {
    __shared__ float row[DO];
    int j = threadIdx.x;
    int i = blockIdx.x;
    row[j] = (i < DO) ? W1b[i * DO + j] : b1b[j];
    __syncthreads();
    float acc = 0.f;
#pragma unroll 8
    for (int k = 0; k < DO; ++k)
        acc += row[k] * W2a[(DN + k) * DO + j];
    if (i < DO) g_Wc[i * DO + j] = acc;
    else        g_c2[j] = acc;
}

// ---------------- kernel 2: precompute via MMA + zeroing + inline c1 -------
__global__ void __launch_bounds__(256, 1) precompute_mma(
        const float* __restrict__ x,
        const float* __restrict__ W1a,
        const float* __restrict__ W2a,
        const float* __restrict__ b2a,
        const float* __restrict__ b1a,
        const float* __restrict__ u,
        int N) {
    extern __shared__ __align__(16) char smraw[];
    __nv_bfloat16* Xh  = (__nv_bfloat16*)smraw;
    __nv_bfloat16* Xl  = Xh  + 128 * PAD2;
    __nv_bfloat16* Wxh = Xl  + 128 * PAD2;
    __nv_bfloat16* Wxl = Wxh + 128 * PAD2;
    __nv_bfloat16* W2h = Wxl + 128 * PAD2;
    __nv_bfloat16* W2l = W2h + 128 * PAD2;
    float* b2as = (float*)(W2l + 128 * PAD2);
    float* c1s  = b2as + DO;

    int tid = threadIdx.x;

    // ---- zero scatter buffers ----
    {
        int gid = blockIdx.x * blockDim.x + tid;
        int gth = gridDim.x * blockDim.x;
        float4 z = make_float4(0.f, 0.f, 0.f, 0.f);
        int nq = N * DO / 4;
        for (int i = gid; i < nq; i += gth) ((float4*)g_sums)[i] = z;
        for (int i = gid; i < N;  i += gth) g_cnt[i] = 0.f;
    }

    for (int idx = tid; idx < DO * DN; idx += 256) {
        int k = idx >> 7, o = idx & 127;
        float v = W1a[idx];
        __nv_bfloat16 h = __float2bfloat16(v);
        Wxh[o * PAD2 + k] = h;
        Wxl[o * PAD2 + k] = __float2bfloat16(v - __bfloat162float(h));
        float w = W2a[idx];
        __nv_bfloat16 h2 = __float2bfloat16(w);
        W2h[o * PAD2 + k] = h2;
        W2l[o * PAD2 + k] = __float2bfloat16(w - __bfloat162float(h2));
    }
    if (tid < DO) {
        b2as[tid] = b2a[tid];
        float acc = b1a[tid];                       // inline c1
#pragma unroll
        for (int k = 0; k < DG; ++k)
            acc += u[k] * W1a[(DN + DE + k) * DO + tid];
        c1s[tid] = acc;
    }
    __syncthreads();

    uint32_t sXh  = (uint32_t)__cvta_generic_to_shared(Xh);
    uint32_t sXl  = (uint32_t)__cvta_generic_to_shared(Xl);
    uint32_t sWxh = (uint32_t)__cvta_generic_to_shared(Wxh);
    uint32_t sWxl = (uint32_t)__cvta_generic_to_shared(Wxl);
    uint32_t sW2h = (uint32_t)__cvta_generic_to_shared(W2h);
    uint32_t sW2l = (uint32_t)__cvta_generic_to_shared(W2l);

    int warp = tid >> 5, lane = tid & 31;
    int R = warp * 16, qr = lane >> 2, qc = lane & 3;
    const float2* b2f2 = (const float2*)b2as;
    const float2* c1f2 = (const float2*)c1s;

    int srow = tid >> 1, skb = (tid & 1) * 64;
    int ntiles = (N + 127) >> 7;
    for (int tile = blockIdx.x; tile < ntiles; tile += gridDim.x) {
        int base = tile << 7;
        {
            int node = base + srow; if (node >= N) node = N - 1;
            const float4* s = (const float4*)(x + (size_t)node * DN + skb);
            ull* ph = (ull*)(Xh + srow * PAD2 + skb);
            ull* pl = (ull*)(Xl + srow * PAD2 + skb);
#pragma unroll
            for (int j = 0; j < 16; ++j) f4_to_hl(s[j], ph[j], pl[j]);
        }
        __syncwarp();

        float d[16][4];
#pragma unroll
        for (int t = 0; t < 16; ++t) d[t][0] = d[t][1] = d[t][2] = d[t][3] = 0.f;
        gemm_hl(sXh, sXl, sWxh, sWxl, R, lane, d, 8, PAD2);
#pragma unroll
        for (int half = 0; half < 2; ++half) {
            int node = base + R + qr + half * 8;
            if (node < N) {
                float2* o = (float2*)(g_xw1 + (size_t)node * DO);
#pragma unroll
                for (int t = 0; t < 16; ++t) {
                    float2 cv = c1f2[t * 4 + qc];
                    o[t * 4 + qc] = make_float2(d[t][half * 2] + cv.x,
                                                d[t][half * 2 + 1] + cv.y);
                }
            }
        }
#pragma unroll
        for (int t = 0; t < 16; ++t) d[t][0] = d[t][1] = d[t][2] = d[t][3] = 0.f;
        gemm_hl(sXh, sXl, sW2h, sW2l, R, lane, d, 8, PAD2);
#pragma unroll
        for (int half = 0; half < 2; ++half) {
            int node = base + R + qr + half * 8;
            if (node < N) {
                float2* o = (float2*)(g_xw2 + (size_t)node * DO);
#pragma unroll
                for (int t = 0; t < 16; ++t) {
                    float2 b = b2f2[t * 4 + qc];
                    o[t * 4 + qc] = make_float2(d[t][half * 2] + b.x,
                                                d[t][half * 2 + 1] + b.y);
                }
            }
        }
        __syncwarp();
    }
}

// ---------------- kernel 3: edge phase (fp16 2-term, 32 edges/warp) --------
// D = EA_hi@W_hi + EA_lo@W_hi  (drop EA_hi@W_lo: ~2^-11.5 relative)
__global__ void __launch_bounds__(256, 1) edge_kernel(
        const int*   __restrict__ ei,
        const float* __restrict__ ea,
        const float* __restrict__ W1a,
        const float* __restrict__ g1,
        const float* __restrict__ be1,
        int E) {
    extern __shared__ __align__(16) char smraw[];
    __half* EAh = (__half*)smraw;                 // 256*PAD
    __half* EAl = EAh + 256 * PAD;
    __half* WTh = EAl + 256 * PAD;                // 128*PAD (hi only)
    float* g1s  = (float*)(WTh + 128 * PAD);
    float* be1s = g1s + 128;
    int*   sd   = (int*)(be1s + 128);             // 256
    int*   dd   = sd + 256;

    int tid = threadIdx.x;
    for (int idx = tid; idx < DE * DO; idx += 256) {
        int k = idx >> 7, o = idx & 127;
        WTh[o * PAD + k] = __float2half(W1a[(DN + k) * DO + o]);
    }
    if (tid < 128) {
        g1s [tid] = g1 [tid];
        be1s[tid] = be1[tid];
    }
    __syncthreads();   // weights + LN vectors visible (once)

    uint32_t sEAh = (uint32_t)__cvta_generic_to_shared(EAh);
    uint32_t sEAl = (uint32_t)__cvta_generic_to_shared(EAl);
    uint32_t sWTh = (uint32_t)__cvta_generic_to_shared(WTh);

    int warp = tid >> 5, lane = tid & 31;
    int R2 = warp * 32;
    int qr = lane >> 2, qc = lane & 3;

    const float2* g1f2  = (const float2*)g1s;
    const float2* be1f2 = (const float2*)be1s;

    uint32_t aoff0 = (uint32_t)(((R2 + (lane & 15)) * PAD + ((lane >> 4) << 3)) * 2);
    uint32_t aoff1 = aoff0 + (uint32_t)(16 * PAD * 2);
    int m = lane >> 3;
    uint32_t boff = (uint32_t)((((m >> 1) * 8 + (lane & 7)) * PAD + ((m & 1) << 3)) * 2);

    int kb = (lane & 1) * 32;

    int ntiles = (E + 255) >> 8;
    for (int tile = blockIdx.x; tile < ntiles; tile += gridDim.x) {
        int base = tile << 8;
        __syncwarp();

        // ---- stage own 32 EA rows (fp16 hi/lo) + own sd/dd ----
#pragma unroll
        for (int p = 0; p < 2; ++p) {
            int e_loc = R2 + p * 16 + (lane >> 1);
            int eg = base + e_loc; if (eg >= E) eg = E - 1;
            const float4* s = (const float4*)(ea + (size_t)eg * DE + kb);
            ull* ph = (ull*)(EAh + e_loc * PAD + kb);
            ull* pl = (ull*)(EAl + e_loc * PAD + kb);
#pragma unroll
            for (int j = 0; j < 8; ++j) f4_to_hl_h(s[j], ph[j], pl[j]);
        }
        {
            int eg2 = base + R2 + lane; if (eg2 >= E) eg2 = E - 1;
            sd[R2 + lane] = ei[eg2];
            dd[R2 + lane] = ei[E + eg2];
        }
        __syncwarp();

        // ---- MMA: 2 groups, fp16, 8 MMAs per (ks,tt) ----
        float d0[16][4], d1[16][4];
#pragma unroll
        for (int t = 0; t < 16; ++t) {
            d0[t][0] = d0[t][1] = d0[t][2] = d0[t][3] = 0.f;
            d1[t][0] = d1[t][1] = d1[t][2] = d1[t][3] = 0.f;
        }
#pragma unroll
        for (int ks = 0; ks < 4; ++ks) {
            uint32_t ka = (uint32_t)(ks * 16 * 2);
            uint32_t a0h0, a0h1, a0h2, a0h3, a0l0, a0l1, a0l2, a0l3;
            uint32_t a1h0, a1h1, a1h2, a1h3, a1l0, a1l1, a1l2, a1l3;
            ldsm_x4(a0h0, a0h1, a0h2, a0h3, sEAh + aoff0 + ka);
            ldsm_x4(a0l0, a0l1, a0l2, a0l3, sEAl + aoff0 + ka);
            ldsm_x4(a1h0, a1h1, a1h2, a1h3, sEAh + aoff1 + ka);
            ldsm_x4(a1l0, a1l1, a1l2, a1l3, sEAl + aoff1 + ka);
#pragma unroll
            for (int tt = 0; tt < 8; ++tt) {
                uint32_t bo = boff + (uint32_t)(tt * 16 * PAD * 2) + ka;
                uint32_t bh0, bh1, bh2, bh3;
                ldsm_x4(bh0, bh1, bh2, bh3, sWTh + bo);
                int t0 = 2 * tt, t1 = 2 * tt + 1;
                mma16816h(d0[t0][0], d0[t0][1], d0[t0][2], d0[t0][3], a0h0, a0h1, a0h2, a0h3, bh0, bh1);
                mma16816h(d0[t0][0], d0[t0][1], d0[t0][2], d0[t0][3], a0l0, a0l1, a0l2, a0l3, bh0, bh1);
                mma16816h(d0[t1][0], d0[t1][1], d0[t1][2], d0[t1][3], a0h0, a0h1, a0h2, a0h3, bh2, bh3);
                mma16816h(d0[t1][0], d0[t1][1], d0[t1][2], d0[t1][3], a0l0, a0l1, a0l2, a0l3, bh2, bh3);
                mma16816h(d1[t0][0], d1[t0][1], d1[t0][2], d1[t0][3], a1h0, a1h1, a1h2, a1h3, bh0, bh1);
                mma16816h(d1[t0][0], d1[t0][1], d1[t0][2], d1[t0][3], a1l0, a1l1, a1l2, a1l3, bh0, bh1);
                mma16816h(d1[t1][0], d1[t1][1], d1[t1][2], d1[t1][3], a1h0, a1h1, a1h2, a1h3, bh2, bh3);
                mma16816h(d1[t1][0], d1[t1][1], d1[t1][2], d1[t1][3], a1l0, a1l1, a1l2, a1l3, bh2, bh3);
            }
        }

        // ---- epilogue: 4 edge rows per lane (2 groups x 2 halves) ----
#pragma unroll
        for (int g = 0; g < 2; ++g) {
            float (*d)[4] = g ? d1 : d0;
#pragma unroll
            for (int half = 0; half < 2; ++half) {
                int r   = R2 + g * 16 + qr + half * 8;
                int src = sd[r], dst = dd[r];
                const float2* bx = (const float2*)(g_xw1 + (size_t)src * DO);

                float sum = 0.f;
#pragma unroll
                for (int t = 0; t < 16; ++t) {
                    float2 b = __ldg(bx + t * 4 + qc);
                    float v0 = d[t][half * 2 + 0] + b.x;
                    float v1 = d[t][half * 2 + 1] + b.y;
                    v0 = v0 >= 0.f ? v0 : NEG_SLOPE * v0;
                    v1 = v1 >= 0.f ? v1 : NEG_SLOPE * v1;
                    d[t][half * 2 + 0] = v0;
                    d[t][half * 2 + 1] = v1;
                    sum += v0 + v1;
                }
                sum += __shfl_xor_sync(0xffffffffu, sum, 1);
                sum += __shfl_xor_sync(0xffffffffu, sum, 2);
                float mu = sum * (1.0f / DO);

                float vv = 0.f;
#pragma unroll
                for (int t = 0; t < 16; ++t) {
                    float e0 = d[t][half * 2 + 0] - mu;
                    float e1 = d[t][half * 2 + 1] - mu;
                    vv += e0 * e0 + e1 * e1;
                }
                vv += __shfl_xor_sync(0xffffffffu, vv, 1);
                vv += __shfl_xor_sync(0xffffffffu, vv, 2);
                float inv = rsqrtf(vv * (1.0f / DO) + LN_EPS);

                if (base + r < E) {
                    float* p = g_sums + (size_t)dst * DO;
#pragma unroll
                    for (int t = 0; t < 16; ++t) {
                        float2 gv = g1f2[t * 4 + qc];
                        float2 bv = be1f2[t * 4 + qc];
                        float t0 = (d[t][half * 2 + 0] - mu) * inv * gv.x + bv.x;
                        float t1 = (d[t][half * 2 + 1] - mu) * inv * gv.y + bv.y;
                        asm volatile("red.global.add.v2.f32 [%0], {%1, %2};"
                                     :: "l"(p + t * 8 + qc * 2), "f"(t0), "f"(t1) : "memory");
                    }
                    if (qc == 0) atomicAdd(g_cnt + dst, 1.0f);
                }
            }
        }
    }
}

// ---------------- kernel 4: fused node MLP via MMA (unchanged) -------------
__global__ void __launch_bounds__(256, 1) node_fused(
        const float* __restrict__ W2b,
        const float* __restrict__ g2,
        const float* __restrict__ be2,
        const float* __restrict__ b2b,
        float* __restrict__ out,
        int N) {
    extern __shared__ __align__(16) char smraw[];
    __nv_bfloat16* Th  = (__nv_bfloat16*)smraw;
    __nv_bfloat16* Tl  = Th  + 128 * PAD2;
    __nv_bfloat16* Wch = Tl  + 128 * PAD2;
    __nv_bfloat16* Wcl = Wch + 128 * PAD2;
    __nv_bfloat16* Wbh = Wcl + 128 * PAD2;
    __nv_bfloat16* Wbl = Wbh + 128 * PAD2;
    float* cs   = (float*)(Wbl + 128 * PAD2);
    float* c2s  = cs  + 128;
    float* g2s  = c2s + 128;
    float* be2s = g2s + 128;
    float* b2bs = be2s + 128;

    int tid = threadIdx.x;
    for (int idx = tid; idx < DO * DO; idx += 256) {
        int k = idx >> 7, o = idx & 127;
        float v = g_Wc[idx];
        __nv_bfloat16 h = __float2bfloat16(v);
        Wch[o * PAD2 + k] = h;
        Wcl[o * PAD2 + k] = __float2bfloat16(v - __bfloat162float(h));
        float w = W2b[idx];
        __nv_bfloat16 h2 = __float2bfloat16(w);
        Wbh[o * PAD2 + k] = h2;
        Wbl[o * PAD2 + k] = __float2bfloat16(w - __bfloat162float(h2));
    }
    if (tid < DO) {
        c2s [tid] = g_c2[tid];
        g2s [tid] = g2 [tid];
        be2s[tid] = be2[tid];
        b2bs[tid] = b2b[tid];
    }
    __syncthreads();

    uint32_t sTh  = (uint32_t)__cvta_generic_to_shared(Th);
    uint32_t sTl  = (uint32_t)__cvta_generic_to_shared(Tl);
    uint32_t sWch = (uint32_t)__cvta_generic_to_shared(Wch);
    uint32_t sWcl = (uint32_t)__cvta_generic_to_shared(Wcl);
    uint32_t sWbh = (uint32_t)__cvta_generic_to_shared(Wbh);
    uint32_t sWbl = (uint32_t)__cvta_generic_to_shared(Wbl);

    int warp = tid >> 5, lane = tid & 31;
    int R = warp * 16, qr = lane >> 2, qc = lane & 3;
    const float2* c2f2  = (const float2*)c2s;
    const float2* g2f2  = (const float2*)g2s;
    const float2* be2f2 = (const float2*)be2s;
    const float2* b2bf2 = (const float2*)b2bs;

    int srow = tid >> 1, skb = (tid & 1) * 64;
    int ntiles = (N + 127) >> 7;
    for (int tile = blockIdx.x; tile < ntiles; tile += gridDim.x) {
        int base = tile << 7;
        {
            int node = base + srow; if (node >= N) node = N - 1;
            float cn = g_cnt[node];
            float ic = cn > 0.f ? (1.0f / cn) : 0.f;
            if ((tid & 1) == 0) cs[srow] = cn;
            const float4* s = (const float4*)(g_sums + (size_t)node * DO + skb);
            ull* ph = (ull*)(Th + srow * PAD2 + skb);
            ull* pl = (ull*)(Tl + srow * PAD2 + skb);
#pragma unroll
            for (int j = 0; j < 16; ++j) {
                float4 v = s[j];
                v.x *= ic; v.y *= ic; v.z *= ic; v.w *= ic;
                f4_to_hl(v, ph[j], pl[j]);
            }
        }
        __syncwarp();

        float d[16][4];
#pragma unroll
        for (int t = 0; t < 16; ++t) d[t][0] = d[t][1] = d[t][2] = d[t][3] = 0.f;
        gemm_hl(sTh, sTl, sWch, sWcl, R, lane, d, 8, PAD2);
        __syncwarp();

#pragma unroll
        for (int half = 0; half < 2; ++half) {
            int r = R + qr + half * 8;
            int node = base + r; if (node >= N) node = N - 1;
            float cnr = cs[r];
            const float2* xw = (const float2*)(g_xw2 + (size_t)node * DO);

            float sum = 0.f;
#pragma unroll
            for (int t = 0; t < 16; ++t) {
                float2 b  = __ldg(xw + t * 4 + qc);
                float2 cv = c2f2[t * 4 + qc];
                float add0 = cnr > 0.f ? cv.x : 0.f;
                float add1 = cnr > 0.f ? cv.y : 0.f;
                float v0 = d[t][half * 2 + 0] + b.x + add0;
                float v1 = d[t][half * 2 + 1] + b.y + add1;
                v0 = v0 >= 0.f ? v0 : NEG_SLOPE * v0;
                v1 = v1 >= 0.f ? v1 : NEG_SLOPE * v1;
                d[t][half * 2 + 0] = v0;
                d[t][half * 2 + 1] = v1;
                sum += v0 + v1;
            }
            sum += __shfl_xor_sync(0xffffffffu, sum, 1);
            sum += __shfl_xor_sync(0xffffffffu, sum, 2);
            float mu = sum * (1.0f / DO);

            float vv = 0.f;
#pragma unroll
            for (int t = 0; t < 16; ++t) {
                float e0 = d[t][half * 2 + 0] - mu;
                float e1 = d[t][half * 2 + 1] - mu;
                vv += e0 * e0 + e1 * e1;
            }
            vv += __shfl_xor_sync(0xffffffffu, vv, 1);
            vv += __shfl_xor_sync(0xffffffffu, vv, 2);
            float inv = rsqrtf(vv * (1.0f / DO) + LN_EPS);

#pragma unroll
            for (int t = 0; t < 16; ++t) {
                float2 gv = g2f2[t * 4 + qc];
                float2 bv = be2f2[t * 4 + qc];
                float t0 = (d[t][half * 2 + 0] - mu) * inv * gv.x + bv.x;
                float t1 = (d[t][half * 2 + 1] - mu) * inv * gv.y + bv.y;
                __nv_bfloat16 h0 = __float2bfloat16(t0);
                __nv_bfloat16 h1 = __float2bfloat16(t1);
                int off = r * PAD2 + t * 8 + 2 * qc;
                *(uint32_t*)(Th + off) = bfpair(t0, t1);
                *(uint32_t*)(Tl + off) = bfpair(t0 - __bfloat162float(h0),
                                                t1 - __bfloat162float(h1));
            }
        }
        __syncwarp();

#pragma unroll
        for (int t = 0; t < 16; ++t) d[t][0] = d[t][1] = d[t][2] = d[t][3] = 0.f;
        gemm_hl(sTh, sTl, sWbh, sWbl, R, lane, d, 8, PAD2);

#pragma unroll
        for (int half = 0; half < 2; ++half) {
            int node = base + R + qr + half * 8;
            if (node < N) {
                float2* o = (float2*)(out + (size_t)node * DO);
#pragma unroll
                for (int t = 0; t < 16; ++t) {
                    float2 b = b2bf2[t * 4 + qc];
                    o[t * 4 + qc] = make_float2(d[t][half * 2] + b.x,
                                                d[t][half * 2 + 1] + b.y);
                }
            }
        }
        __syncwarp();
    }
}

// ---------------- launcher -------------------------------------------------
static bool g_attr_done = false;

extern "C" void kernel_launch(void* const* d_in, const int* in_sizes, int n_in,
                              void* d_out, int out_size) {
    const float* x   = (const float*)d_in[0];
    const int*   ei  = (const int*)  d_in[1];
    const float* ea  = (const float*)d_in[2];
    const float* u   = (const float*)d_in[3];
    const float* W1a = (const float*)d_in[5];
    const float* b1a = (const float*)d_in[6];
    const float* g1  = (const float*)d_in[7];
    const float* be1 = (const float*)d_in[8];
    const float* W1b = (const float*)d_in[9];
    const float* b1b = (const float*)d_in[10];
    const float* W2a = (const float*)d_in[11];
    const float* b2a = (const float*)d_in[12];
    const float* g2  = (const float*)d_in[13];
    const float* be2 = (const float*)d_in[14];
    const float* W2b = (const float*)d_in[15];
    const float* b2b = (const float*)d_in[16];
    float* out = (float*)d_out;

    int N = in_sizes[0] / DN;
    int E = in_sizes[2] / DE;

    const int PRE2_SMEM = 6 * 128 * PAD2 * 2 + 2 * 128 * 4;                    // 209536
    const int EDGE_SMEM = (2 * 256 + 128) * PAD * 2 + 2 * 128 * 4 + 2 * 256 * 4; // 95232
    const int NF_SMEM   = 6 * 128 * PAD2 * 2 + 5 * 128 * 4;                    // 211456

    if (!g_attr_done) {
        cudaFuncSetAttribute(precompute_mma, cudaFuncAttributeMaxDynamicSharedMemorySize, PRE2_SMEM);
        cudaFuncSetAttribute(edge_kernel,    cudaFuncAttributeMaxDynamicSharedMemorySize, EDGE_SMEM);
        cudaFuncSetAttribute(node_fused,     cudaFuncAttributeMaxDynamicSharedMemorySize, NF_SMEM);
        g_attr_done = true;
    }

    wc_kernel<<<129, 128>>>(W1b, b1b, W2a);
    precompute_mma<<<148, 256, PRE2_SMEM>>>(x, W1a, W2a, b2a, b1a, u, N);
    edge_kernel<<<148, 256, EDGE_SMEM>>>(ei, ea, W1a, g1, be1, E);
    node_fused<<<148, 256, NF_SMEM>>>(W2b, g2, be2, b2b, out, N);
}